// round 12
// baseline (speedup 1.0000x reference)
#include <cuda_runtime.h>
#include <cuda_bf16.h>
#include <cuda_fp16.h>
#include <cstdint>

#define BATCH 8
#define TSEQ 1024
#define DMOD 1024
#define NH 8
#define DH 128
#define SCALE 0.08838834764831845f

__device__ __half g_Xh[BATCH * TSEQ * DMOD];
__device__ __half g_Wh[3 * DMOD * DMOD];
__device__ __half g_Qh[BATCH * TSEQ * DMOD];
__device__ __half g_Kh[BATCH * TSEQ * DMOD];
__device__ __half g_Vh[BATCH * TSEQ * DMOD];

__device__ __forceinline__ uint32_t smem_u32(const void* p) {
    uint32_t a;
    asm("{ .reg .u64 t; cvta.to.shared.u64 t, %1; cvt.u32.u64 %0, t; }"
        : "=r"(a) : "l"(p));
    return a;
}
__device__ __forceinline__ void cp16(uint32_t dst, const void* src) {
    asm volatile("cp.async.cg.shared.global [%0], [%1], 16;"
                 :: "r"(dst), "l"(src) : "memory");
}
#define CP_COMMIT() asm volatile("cp.async.commit_group;" ::: "memory")
#define CP_WAIT(n)  asm volatile("cp.async.wait_group %0;" :: "n"(n) : "memory")

#define MMA_F16(c, a, b0_, b1_) \
    asm volatile("mma.sync.aligned.m16n8k16.row.col.f32.f16.f16.f32 " \
                 "{%0,%1,%2,%3}, {%4,%5,%6,%7}, {%8,%9}, {%0,%1,%2,%3};" \
                 : "+f"((c)[0]), "+f"((c)[1]), "+f"((c)[2]), "+f"((c)[3]) \
                 : "r"((a)[0]), "r"((a)[1]), "r"((a)[2]), "r"((a)[3]), \
                   "r"(b0_), "r"(b1_))

#define LDMX4(r, addr) \
    asm volatile("ldmatrix.sync.aligned.m8n8.x4.shared.b16 {%0,%1,%2,%3}, [%4];" \
                 : "=r"((r)[0]), "=r"((r)[1]), "=r"((r)[2]), "=r"((r)[3]) : "r"(addr))
#define LDMX4T(r, addr) \
    asm volatile("ldmatrix.sync.aligned.m8n8.x4.trans.shared.b16 {%0,%1,%2,%3}, [%4];" \
                 : "=r"((r)[0]), "=r"((r)[1]), "=r"((r)[2]), "=r"((r)[3]) : "r"(addr))

__device__ __forceinline__ uint32_t hmul2u(uint32_t a, uint32_t b) {
    uint32_t d;
    asm("mul.rn.f16x2 %0, %1, %2;" : "=r"(d) : "r"(a), "r"(b));
    return d;
}

// ===========================================================================
// One fused conversion launch: X (8192 blocks) then Wq/Wk/Wv (1024 each).
// ===========================================================================
__global__ __launch_bounds__(256) void cvt_all(const float4* __restrict__ x,
                                               const float4* __restrict__ w0,
                                               const float4* __restrict__ w1,
                                               const float4* __restrict__ w2,
                                               uint2* __restrict__ xh,
                                               uint2* __restrict__ wh) {
    int bi = blockIdx.x;
    const float4* src;
    uint2* dst;
    int i;
    if (bi < 8192) {
        i = bi * 256 + threadIdx.x;
        src = x;
        dst = xh;
    } else {
        int wsel = (bi - 8192) >> 10;
        i = ((bi - 8192) & 1023) * 256 + threadIdx.x;
        src = (wsel == 0) ? w0 : (wsel == 1) ? w1 : w2;
        dst = wh + (size_t)wsel * (DMOD * DMOD / 4);
    }
    float4 v = src[i];
    __half2 p01 = __floats2half2_rn(v.x, v.y);
    __half2 p23 = __floats2half2_rn(v.z, v.w);
    uint2 H;
    H.x = *(uint32_t*)&p01;
    H.y = *(uint32_t*)&p23;
    dst[i] = H;
}

// ===========================================================================
// Fused QKV GEMM (at mma.sync floor). SCALE folded into Q epilogue.
// ===========================================================================
#define GTILE 10240
#define GSTAGE (2 * GTILE)
#define GEMM_SMEM (2 * GSTAGE)

__global__ __launch_bounds__(256, 2) void gemm_qkv_f16(
    const __half* __restrict__ Xh, const __half* __restrict__ Wh,
    __half* __restrict__ qh, __half* __restrict__ kh, __half* __restrict__ vh) {
    extern __shared__ char smc[];
    const uint32_t sb = smem_u32(smc);

    const int tid = threadIdx.x;
    const int lane = tid & 31, wid = tid >> 5;
    const int bm = blockIdx.y << 7;
    const int bnG = blockIdx.x << 7;
    const int wm = (wid & 1) * 64, wn = (wid >> 1) * 32;
    const int fm = lane >> 2;
    const int fkb = (lane & 3) * 4;
    const int grp = lane >> 3, li = lane & 7;

    float acc[4][4][4];
#pragma unroll
    for (int i = 0; i < 4; i++)
#pragma unroll
        for (int j = 0; j < 4; j++)
#pragma unroll
            for (int q = 0; q < 4; q++) acc[i][j][q] = 0.f;

    const int c0row = tid >> 2;
    const int c1row = c0row + 64;
    const int ce = (tid & 3) * 8;
    const uint32_t d0 = (uint32_t)(c0row * 80 + (tid & 3) * 16);
    const uint32_t d1 = (uint32_t)(c1row * 80 + (tid & 3) * 16);

#define ISSUE_STAGE(kt, p) do {                                        \
    uint32_t s0 = sb + (p) * GSTAGE;                                   \
    size_t a0 = (size_t)(bm + c0row) * 1024 + (size_t)(kt) * 32 + ce;  \
    size_t a1 = (size_t)(bm + c1row) * 1024 + (size_t)(kt) * 32 + ce;  \
    size_t b0 = (size_t)(bnG + c0row) * 1024 + (size_t)(kt) * 32 + ce; \
    size_t b1 = (size_t)(bnG + c1row) * 1024 + (size_t)(kt) * 32 + ce; \
    cp16(s0 + d0,         Xh + a0);  cp16(s0 + d1,         Xh + a1);   \
    cp16(s0 + GTILE + d0, Wh + b0);  cp16(s0 + GTILE + d1, Wh + b1);   \
    CP_COMMIT();                                                       \
} while (0)

    ISSUE_STAGE(0, 0);

    for (int kt = 0; kt < 32; kt++) {
        const int p = kt & 1;
        if (kt < 31) {
            ISSUE_STAGE(kt + 1, p ^ 1);
            CP_WAIT(1);
        } else {
            CP_WAIT(0);
        }
        __syncthreads();

        const uint32_t st = sb + p * GSTAGE;
#pragma unroll
        for (int k16o = 0; k16o < 64; k16o += 32) {
            uint32_t ah[4][4], bh[2][4];
            const uint32_t akb = (uint32_t)(k16o + ((grp >> 1) << 4));
            const uint32_t bkb = (uint32_t)(k16o + ((grp & 1) << 4));
#pragma unroll
            for (int np = 0; np < 2; np++) {
                uint32_t nrow = (uint32_t)(wn + np * 16 + ((grp >> 1) << 3) + li);
                LDMX4(bh[np], st + GTILE + nrow * 80 + bkb);
            }
#pragma unroll
            for (int mt = 0; mt < 4; mt++) {
                uint32_t arow = (uint32_t)(wm + mt * 16 + ((grp & 1) << 3) + li);
                LDMX4(ah[mt], st + arow * 80 + akb);
            }
#pragma unroll
            for (int mt = 0; mt < 4; mt++)
#pragma unroll
                for (int nt = 0; nt < 4; nt++)
                    MMA_F16(acc[mt][nt], ah[mt], bh[nt >> 1][(nt & 1) * 2],
                            bh[nt >> 1][(nt & 1) * 2 + 1]);
        }
        __syncthreads();
    }

    const int which = bnG >> 10;
    const int nloc = bnG & 1023;
    __half* C = (which == 0) ? qh : (which == 1) ? kh : vh;
    const float escl = (which == 0) ? SCALE : 1.f;

#pragma unroll
    for (int mt = 0; mt < 4; mt++) {
        size_t m0 = (size_t)(bm + wm + mt * 16 + fm);
#pragma unroll
        for (int nt = 0; nt < 4; nt++) {
            size_t n0 = (size_t)(nloc + wn + nt * 8 + (fkb >> 1));
            __half2 p01 = __floats2half2_rn(acc[mt][nt][0] * escl, acc[mt][nt][1] * escl);
            __half2 p23 = __floats2half2_rn(acc[mt][nt][2] * escl, acc[mt][nt][3] * escl);
            *(uint32_t*)((char*)C + (m0 * 1024 + n0) * 2) = *(uint32_t*)&p01;
            *(uint32_t*)((char*)C + ((m0 + 8) * 1024 + n0) * 2) = *(uint32_t*)&p23;
        }
    }
}

// ===========================================================================
// Flash attention: Q frags persistent in regs, split-k PV (P never in smem),
// fused single-sync softmax, 3-stage cp.async KV pipeline, 1 CTA/SM.
// ===========================================================================
#define A_QH 0
#define A_ST 17408
#define ST_SZ 34816
#define A_MX (A_ST + 3 * ST_SZ)        // 121856
#define A_SU (A_MX + 512)
#define ATTN_SMEM (A_SU + 512)         // 122880

__global__ __launch_bounds__(256, 1) void attn_tc(const float* __restrict__ mask,
                                                  float* __restrict__ out) {
    extern __shared__ char smc[];
    const uint32_t sb = smem_u32(smc);

    const int tid = threadIdx.x;
    const int lane = tid & 31, wid = tid >> 5;
    const int qt = (blockIdx.x == 0) ? 15 : (int)blockIdx.x - 1;
    const int h = blockIdx.y, b = blockIdx.z;
    const int wm = (wid & 3) * 16;
    const int cg = wid >> 2;             // S col half / PV k half
    const int fm = lane >> 2, q = lane & 3;
    const int grp = lane >> 3, li = lane & 7;
    const int r0 = wm + fm, r1 = r0 + 8;

    const size_t bh_off = (size_t)b * TSEQ * DMOD + (size_t)h * DH;
    const __half* Qh = g_Qh + bh_off;
    const __half* Kh = g_Kh + bh_off;
    const __half* Vh = g_Vh + bh_off;

    const int kt0 = (qt == 15) ? 0 : qt;

    // Q tile -> smem (group 0)
    for (int c = tid; c < 1024; c += 256) {
        int r = c >> 4, o = c & 15;
        cp16(sb + A_QH + (uint32_t)(r * 272 + o * 16),
             Qh + (size_t)(qt * 64 + r) * DMOD + o * 8);
    }
    CP_COMMIT();

#define ISSUE_KV(kt_, s_) do {                                           \
    uint32_t kst = sb + A_ST + (uint32_t)(s_) * ST_SZ;                   \
    size_t roff = (size_t)(kt_) * 64 * DMOD;                             \
    for (int c = tid; c < 1024; c += 256) {                              \
        int r = c >> 4, o = c & 15;                                      \
        uint32_t d = (uint32_t)(r * 272 + o * 16);                       \
        size_t g = roff + (size_t)r * DMOD + o * 8;                      \
        cp16(kst + d,         Kh + g);                                   \
        cp16(kst + 17408 + d, Vh + g);                                   \
    }                                                                    \
} while (0)

#pragma unroll
    for (int s = 0; s < 3; s++) {
        if (kt0 + s <= 15) ISSUE_KV(kt0 + s, s);
        CP_COMMIT();
    }

    CP_WAIT(3);                 // Q group done
    __syncthreads();

    // Persistent Q fragments
    uint32_t Qf[8][4];
    {
        uint32_t arow = (uint32_t)(wm + ((grp & 1) << 3) + li);
#pragma unroll
        for (int ks = 0; ks < 8; ks++) {
            uint32_t akb = (uint32_t)(ks * 32 + ((grp >> 1) << 4));
            LDMX4(Qf[ks], sb + A_QH + arow * 272 + akb);
        }
    }

    float* MX = (float*)(smc + A_MX);
    float* SU = (float*)(smc + A_SU);

    float rowm0 = -1e30f, rowm1 = -1e30f, rowl0 = 0.f, rowl1 = 0.f;
    float acc_o[16][4];
#pragma unroll
    for (int j = 0; j < 16; j++)
#pragma unroll
        for (int qq = 0; qq < 4; qq++) acc_o[j][qq] = 0.f;

    for (int kt = kt0; kt < 16; kt++) {
        const int s = (kt - kt0) % 3;
        const uint32_t kstg = sb + A_ST + (uint32_t)s * ST_SZ;
        const uint32_t vstg = kstg + 17408;

        CP_WAIT(2);
        __syncthreads();                           // stage ready

        // ---- S = Q * K^T ----
        float sacc[4][4];
#pragma unroll
        for (int j = 0; j < 4; j++)
#pragma unroll
            for (int qq = 0; qq < 4; qq++) sacc[j][qq] = 0.f;

#pragma unroll
        for (int ks = 0; ks < 8; ks++) {
            uint32_t bh[2][4];
            uint32_t kb = (uint32_t)(ks * 32 + ((grp & 1) << 4));
#pragma unroll
            for (int j2 = 0; j2 < 2; j2++) {
                uint32_t nrow = (uint32_t)(cg * 32 + j2 * 16 + ((grp >> 1) << 3) + li);
                LDMX4(bh[j2], kstg + nrow * 272 + kb);
            }
#pragma unroll
            for (int j = 0; j < 4; j++)
                MMA_F16(sacc[j], Qf[ks], bh[j >> 1][(j & 1) * 2], bh[j >> 1][(j & 1) * 2 + 1]);
        }

        // ---- causal mask (SCALE already folded into Q) ----
        {
            const int qg0 = qt * 64 + r0, qg1 = qg0 + 8;
#pragma unroll
            for (int j = 0; j < 4; j++) {
                int kg = kt * 64 + cg * 32 + 8 * j + 2 * q;
                sacc[j][0] += (kg     <= qg0) ? -10000.f : 0.f;
                sacc[j][1] += (kg + 1 <= qg0) ? -10000.f : 0.f;
                sacc[j][2] += (kg     <= qg1) ? -10000.f : 0.f;
                sacc[j][3] += (kg + 1 <= qg1) ? -10000.f : 0.f;
            }
        }

        // ---- warp-local row max over 32 cols ----
        float m0 = fmaxf(fmaxf(sacc[0][0], sacc[0][1]), fmaxf(sacc[1][0], sacc[1][1]));
        m0 = fmaxf(m0, fmaxf(fmaxf(sacc[2][0], sacc[2][1]), fmaxf(sacc[3][0], sacc[3][1])));
        float m1 = fmaxf(fmaxf(sacc[0][2], sacc[0][3]), fmaxf(sacc[1][2], sacc[1][3]));
        m1 = fmaxf(m1, fmaxf(fmaxf(sacc[2][2], sacc[2][3]), fmaxf(sacc[3][2], sacc[3][3])));
        m0 = fmaxf(m0, __shfl_xor_sync(0xffffffffu, m0, 1));
        m0 = fmaxf(m0, __shfl_xor_sync(0xffffffffu, m0, 2));
        m1 = fmaxf(m1, __shfl_xor_sync(0xffffffffu, m1, 1));
        m1 = fmaxf(m1, __shfl_xor_sync(0xffffffffu, m1, 2));
        if (q == 0) { MX[cg * 64 + r0] = m0; MX[cg * 64 + r1] = m1; }

        // ---- exp with local max, local sums, pack P frags ----
        uint32_t pf[2][4];
        float s0 = 0.f, s1 = 0.f;
#pragma unroll
        for (int j = 0; j < 4; j++) {
            float p0 = __expf(sacc[j][0] - m0);
            float p1 = __expf(sacc[j][1] - m0);
            float p2 = __expf(sacc[j][2] - m1);
            float p3 = __expf(sacc[j][3] - m1);
            s0 += p0 + p1;
            s1 += p2 + p3;
            __half2 h01 = __floats2half2_rn(p0, p1);
            __half2 h23 = __floats2half2_rn(p2, p3);
            pf[j >> 1][((j & 1) << 1) + 0] = *(uint32_t*)&h01;
            pf[j >> 1][((j & 1) << 1) + 1] = *(uint32_t*)&h23;
        }
        s0 += __shfl_xor_sync(0xffffffffu, s0, 1);
        s0 += __shfl_xor_sync(0xffffffffu, s0, 2);
        s1 += __shfl_xor_sync(0xffffffffu, s1, 1);
        s1 += __shfl_xor_sync(0xffffffffu, s1, 2);
        if (q == 0) { SU[cg * 64 + r0] = s0; SU[cg * 64 + r1] = s1; }
        __syncthreads();                           // stats visible

        // ---- combine stats, rescale ----
        const float mx00 = MX[r0], mx10 = MX[64 + r0];
        const float mx01 = MX[r1], mx11 = MX[64 + r1];
        const float mn0 = fmaxf(rowm0, fmaxf(mx00, mx10));
        const float mn1 = fmaxf(rowm1, fmaxf(mx01, mx11));
        const float alpha0 = __expf(rowm0 - mn0);
        const float alpha1 = __expf(rowm1 - mn1);
        rowl0 = rowl0 * alpha0 + SU[r0] * __expf(mx00 - mn0) + SU[64 + r0] * __expf(mx10 - mn0);
        rowl1 = rowl1 * alpha1 + SU[r1] * __expf(mx01 - mn1) + SU[64 + r1] * __expf(mx11 - mn1);
        rowm0 = mn0;
        rowm1 = mn1;

        const float f0 = __expf(m0 - mn0);
        const float f1 = __expf(m1 - mn1);
        __half2 F0h = __floats2half2_rn(f0, f0);
        __half2 F1h = __floats2half2_rn(f1, f1);
        const uint32_t F0 = *(uint32_t*)&F0h, F1 = *(uint32_t*)&F1h;
#pragma unroll
        for (int kc2 = 0; kc2 < 2; kc2++) {
            pf[kc2][0] = hmul2u(pf[kc2][0], F0);
            pf[kc2][2] = hmul2u(pf[kc2][2], F0);
            pf[kc2][1] = hmul2u(pf[kc2][1], F1);
            pf[kc2][3] = hmul2u(pf[kc2][3], F1);
        }
#pragma unroll
        for (int j = 0; j < 16; j++) {
            acc_o[j][0] *= alpha0; acc_o[j][1] *= alpha0;
            acc_o[j][2] *= alpha1; acc_o[j][3] *= alpha1;
        }

        // ---- O += P(own 32 k-cols) * V ----
#pragma unroll
        for (int kc2 = 0; kc2 < 2; kc2++) {
            uint32_t krow = (uint32_t)(cg * 32 + kc2 * 16 + ((grp & 1) << 3) + li);
#pragma unroll
            for (int nf2 = 0; nf2 < 8; nf2++) {
                uint32_t bvh[4];
                uint32_t nb = (uint32_t)((nf2 * 16 + ((grp >> 1) << 3)) * 2);
                LDMX4T(bvh, vstg + krow * 272 + nb);
                MMA_F16(acc_o[2 * nf2],     pf[kc2], bvh[0], bvh[1]);
                MMA_F16(acc_o[2 * nf2 + 1], pf[kc2], bvh[2], bvh[3]);
            }
        }
        __syncthreads();                           // stage consumed

        if (kt + 3 <= 15) ISSUE_KV(kt + 3, s);
        CP_COMMIT();
    }

    // ---- epilogue: cross-cg reduction through stage0, then store ----
    float* Ored = (float*)(smc + A_ST);
    if (cg == 1) {
#pragma unroll
        for (int nf = 0; nf < 16; nf++) {
            int col = nf * 8 + 2 * q;
            *(float2*)&Ored[r0 * 128 + col] = make_float2(acc_o[nf][0], acc_o[nf][1]);
            *(float2*)&Ored[r1 * 128 + col] = make_float2(acc_o[nf][2], acc_o[nf][3]);
        }
    }
    __syncthreads();
    if (cg == 0) {
        const int grow0 = b * TSEQ + qt * 64 + r0;
        float scl0 = (1.f / rowl0) * mask[(size_t)b * TSEQ + qt * 64 + r0];
        float scl1 = (1.f / rowl1) * mask[(size_t)b * TSEQ + qt * 64 + r1];
#pragma unroll
        for (int nf = 0; nf < 16; nf++) {
            int col = nf * 8 + 2 * q;
            float2 pr0 = *(float2*)&Ored[r0 * 128 + col];
            float2 pr1 = *(float2*)&Ored[r1 * 128 + col];
            float2 w0 = make_float2((acc_o[nf][0] + pr0.x) * scl0,
                                    (acc_o[nf][1] + pr0.y) * scl0);
            float2 w1 = make_float2((acc_o[nf][2] + pr1.x) * scl1,
                                    (acc_o[nf][3] + pr1.y) * scl1);
            *(float2*)&out[(size_t)grow0 * DMOD + h * DH + col] = w0;
            *(float2*)&out[(size_t)(grow0 + 8) * DMOD + h * DH + col] = w1;
        }
    }
}

extern "C" void kernel_launch(void* const* d_in, const int* in_sizes, int n_in,
                              void* d_out, int out_size) {
    const float* x    = (const float*)d_in[0];
    const float* mask = (const float*)d_in[1];
    const float* Wq   = (const float*)d_in[2];
    const float* Wk   = (const float*)d_in[3];
    const float* Wv   = (const float*)d_in[4];
    float* out = (float*)d_out;

    __half *xh, *wh, *qh, *kh, *vh;
    cudaGetSymbolAddress((void**)&xh, g_Xh);
    cudaGetSymbolAddress((void**)&wh, g_Wh);
    cudaGetSymbolAddress((void**)&qh, g_Qh);
    cudaGetSymbolAddress((void**)&kh, g_Kh);
    cudaGetSymbolAddress((void**)&vh, g_Vh);

    cudaFuncSetAttribute(gemm_qkv_f16, cudaFuncAttributeMaxDynamicSharedMemorySize,
                         GEMM_SMEM);
    cudaFuncSetAttribute(attn_tc, cudaFuncAttributeMaxDynamicSharedMemorySize,
                         ATTN_SMEM);

    cvt_all<<<8192 + 3 * 1024, 256>>>((const float4*)x, (const float4*)Wq,
                                      (const float4*)Wk, (const float4*)Wv,
                                      (uint2*)xh, (uint2*)wh);

    dim3 ggrid(3 * DMOD / 128, (BATCH * TSEQ) / 128);
    gemm_qkv_f16<<<ggrid, 256, GEMM_SMEM>>>(xh, wh, qh, kh, vh);

    dim3 agrid(TSEQ / 64, NH, BATCH);
    attn_tc<<<agrid, 256, ATTN_SMEM>>>(mask, out);
}

// round 13
// speedup vs baseline: 1.0378x; 1.0378x over previous
#include <cuda_runtime.h>
#include <cuda_bf16.h>
#include <cuda_fp16.h>
#include <cstdint>

#define BATCH 8
#define TSEQ 1024
#define DMOD 1024
#define NH 8
#define DH 128
#define SCALE 0.08838834764831845f

__device__ __half g_Xh[BATCH * TSEQ * DMOD];
__device__ __half g_Wh[3 * DMOD * DMOD];
__device__ __half g_Qh[BATCH * TSEQ * DMOD];
__device__ __half g_Kh[BATCH * TSEQ * DMOD];
__device__ __half g_Vh[BATCH * TSEQ * DMOD];

__device__ __forceinline__ uint32_t smem_u32(const void* p) {
    uint32_t a;
    asm("{ .reg .u64 t; cvta.to.shared.u64 t, %1; cvt.u32.u64 %0, t; }"
        : "=r"(a) : "l"(p));
    return a;
}
__device__ __forceinline__ void cp16(uint32_t dst, const void* src) {
    asm volatile("cp.async.cg.shared.global [%0], [%1], 16;"
                 :: "r"(dst), "l"(src) : "memory");
}
#define CP_COMMIT() asm volatile("cp.async.commit_group;" ::: "memory")
#define CP_WAIT(n)  asm volatile("cp.async.wait_group %0;" :: "n"(n) : "memory")

#define MMA_F16(c, a, b0_, b1_) \
    asm volatile("mma.sync.aligned.m16n8k16.row.col.f32.f16.f16.f32 " \
                 "{%0,%1,%2,%3}, {%4,%5,%6,%7}, {%8,%9}, {%0,%1,%2,%3};" \
                 : "+f"((c)[0]), "+f"((c)[1]), "+f"((c)[2]), "+f"((c)[3]) \
                 : "r"((a)[0]), "r"((a)[1]), "r"((a)[2]), "r"((a)[3]), \
                   "r"(b0_), "r"(b1_))

#define LDMX4(r, addr) \
    asm volatile("ldmatrix.sync.aligned.m8n8.x4.shared.b16 {%0,%1,%2,%3}, [%4];" \
                 : "=r"((r)[0]), "=r"((r)[1]), "=r"((r)[2]), "=r"((r)[3]) : "r"(addr))
#define LDMX4T(r, addr) \
    asm volatile("ldmatrix.sync.aligned.m8n8.x4.trans.shared.b16 {%0,%1,%2,%3}, [%4];" \
                 : "=r"((r)[0]), "=r"((r)[1]), "=r"((r)[2]), "=r"((r)[3]) : "r"(addr))

// ===========================================================================
// Fused conversion: X (8192 blocks) then Wq/Wk/Wv (1024 each).
// ===========================================================================
__global__ __launch_bounds__(256) void cvt_all(const float4* __restrict__ x,
                                               const float4* __restrict__ w0,
                                               const float4* __restrict__ w1,
                                               const float4* __restrict__ w2,
                                               uint2* __restrict__ xh,
                                               uint2* __restrict__ wh) {
    int bi = blockIdx.x;
    const float4* src;
    uint2* dst;
    int i;
    if (bi < 8192) {
        i = bi * 256 + threadIdx.x;
        src = x;
        dst = xh;
    } else {
        int wsel = (bi - 8192) >> 10;
        i = ((bi - 8192) & 1023) * 256 + threadIdx.x;
        src = (wsel == 0) ? w0 : (wsel == 1) ? w1 : w2;
        dst = wh + (size_t)wsel * (DMOD * DMOD / 4);
    }
    float4 v = src[i];
    __half2 p01 = __floats2half2_rn(v.x, v.y);
    __half2 p23 = __floats2half2_rn(v.z, v.w);
    uint2 H;
    H.x = *(uint32_t*)&p01;
    H.y = *(uint32_t*)&p23;
    dst[i] = H;
}

// ===========================================================================
// Fused QKV GEMM (at mma.sync floor). SCALE folded into Q epilogue.
// ===========================================================================
#define GTILE 10240
#define GSTAGE (2 * GTILE)
#define GEMM_SMEM (2 * GSTAGE)

__global__ __launch_bounds__(256, 2) void gemm_qkv_f16(
    const __half* __restrict__ Xh, const __half* __restrict__ Wh,
    __half* __restrict__ qh, __half* __restrict__ kh, __half* __restrict__ vh) {
    extern __shared__ char smc[];
    const uint32_t sb = smem_u32(smc);

    const int tid = threadIdx.x;
    const int lane = tid & 31, wid = tid >> 5;
    const int bm = blockIdx.y << 7;
    const int bnG = blockIdx.x << 7;
    const int wm = (wid & 1) * 64, wn = (wid >> 1) * 32;
    const int fm = lane >> 2;
    const int fkb = (lane & 3) * 4;
    const int grp = lane >> 3, li = lane & 7;

    float acc[4][4][4];
#pragma unroll
    for (int i = 0; i < 4; i++)
#pragma unroll
        for (int j = 0; j < 4; j++)
#pragma unroll
            for (int q = 0; q < 4; q++) acc[i][j][q] = 0.f;

    const int c0row = tid >> 2;
    const int c1row = c0row + 64;
    const int ce = (tid & 3) * 8;
    const uint32_t d0 = (uint32_t)(c0row * 80 + (tid & 3) * 16);
    const uint32_t d1 = (uint32_t)(c1row * 80 + (tid & 3) * 16);

#define ISSUE_STAGE(kt, p) do {                                        \
    uint32_t s0 = sb + (p) * GSTAGE;                                   \
    size_t a0 = (size_t)(bm + c0row) * 1024 + (size_t)(kt) * 32 + ce;  \
    size_t a1 = (size_t)(bm + c1row) * 1024 + (size_t)(kt) * 32 + ce;  \
    size_t b0 = (size_t)(bnG + c0row) * 1024 + (size_t)(kt) * 32 + ce; \
    size_t b1 = (size_t)(bnG + c1row) * 1024 + (size_t)(kt) * 32 + ce; \
    cp16(s0 + d0,         Xh + a0);  cp16(s0 + d1,         Xh + a1);   \
    cp16(s0 + GTILE + d0, Wh + b0);  cp16(s0 + GTILE + d1, Wh + b1);   \
    CP_COMMIT();                                                       \
} while (0)

    ISSUE_STAGE(0, 0);

    for (int kt = 0; kt < 32; kt++) {
        const int p = kt & 1;
        if (kt < 31) {
            ISSUE_STAGE(kt + 1, p ^ 1);
            CP_WAIT(1);
        } else {
            CP_WAIT(0);
        }
        __syncthreads();

        const uint32_t st = sb + p * GSTAGE;
#pragma unroll
        for (int k16o = 0; k16o < 64; k16o += 32) {
            uint32_t ah[4][4], bh[2][4];
            const uint32_t akb = (uint32_t)(k16o + ((grp >> 1) << 4));
            const uint32_t bkb = (uint32_t)(k16o + ((grp & 1) << 4));
#pragma unroll
            for (int np = 0; np < 2; np++) {
                uint32_t nrow = (uint32_t)(wn + np * 16 + ((grp >> 1) << 3) + li);
                LDMX4(bh[np], st + GTILE + nrow * 80 + bkb);
            }
#pragma unroll
            for (int mt = 0; mt < 4; mt++) {
                uint32_t arow = (uint32_t)(wm + mt * 16 + ((grp & 1) << 3) + li);
                LDMX4(ah[mt], st + arow * 80 + akb);
            }
#pragma unroll
            for (int mt = 0; mt < 4; mt++)
#pragma unroll
                for (int nt = 0; nt < 4; nt++)
                    MMA_F16(acc[mt][nt], ah[mt], bh[nt >> 1][(nt & 1) * 2],
                            bh[nt >> 1][(nt & 1) * 2 + 1]);
        }
        __syncthreads();
    }

    const int which = bnG >> 10;
    const int nloc = bnG & 1023;
    __half* C = (which == 0) ? qh : (which == 1) ? kh : vh;
    const float escl = (which == 0) ? SCALE : 1.f;

#pragma unroll
    for (int mt = 0; mt < 4; mt++) {
        size_t m0 = (size_t)(bm + wm + mt * 16 + fm);
#pragma unroll
        for (int nt = 0; nt < 4; nt++) {
            size_t n0 = (size_t)(nloc + wn + nt * 8 + (fkb >> 1));
            __half2 p01 = __floats2half2_rn(acc[mt][nt][0] * escl, acc[mt][nt][1] * escl);
            __half2 p23 = __floats2half2_rn(acc[mt][nt][2] * escl, acc[mt][nt][3] * escl);
            *(uint32_t*)((char*)C + (m0 * 1024 + n0) * 2) = *(uint32_t*)&p01;
            *(uint32_t*)((char*)C + ((m0 + 8) * 1024 + n0) * 2) = *(uint32_t*)&p23;
        }
    }
}

// ===========================================================================
// Flash attention (R11 structure, verified): register-resident softmax with
// MX/SU exchange; row stats in registers (replicated per warp); 2 CTAs/SM.
// SCALE pre-folded into Q.
// ===========================================================================
#define A_QH 0
#define A_KB 17408
#define KV_STRIDE 17408
#define A_VB 52224
#define A_PH 87040          // P fp16 [64][72] (144B rows)
#define A_MX 96256          // float [2][64]
#define A_SU 96768          // float [2][64]
#define ATTN_SMEM 97280

__global__ __launch_bounds__(256, 2) void attn_tc(const float* __restrict__ mask,
                                                  float* __restrict__ out) {
    extern __shared__ char smc[];
    const uint32_t sb = smem_u32(smc);

    const int tid = threadIdx.x;
    const int lane = tid & 31, wid = tid >> 5;
    const int qt = (blockIdx.x == 0) ? 15 : (int)blockIdx.x - 1;
    const int h = blockIdx.y, b = blockIdx.z;
    const int wm = (wid & 3) * 16;
    const int cg = wid >> 2;
    const int wnS = cg * 32;
    const int wnV = cg * 64;
    const int fm = lane >> 2, q = lane & 3;
    const int grp = lane >> 3, li = lane & 7;
    const int r0 = wm + fm, r1 = r0 + 8;

    const size_t bh_off = (size_t)b * TSEQ * DMOD + (size_t)h * DH;
    const __half* Qh = g_Qh + bh_off;
    const __half* Kh = g_Kh + bh_off;
    const __half* Vh = g_Vh + bh_off;

    const int kt0 = (qt == 15) ? 0 : qt;

    for (int c = tid; c < 1024; c += 256) {
        int r = c >> 4, o = c & 15;
        uint32_t d = (uint32_t)(r * 272 + o * 16);
        size_t g = (size_t)(qt * 64 + r) * DMOD + o * 8;
        cp16(sb + A_QH + d, Qh + g);
    }

#define ISSUE_KV(kt_, s_) do {                                           \
    uint32_t kst = sb + A_KB + (uint32_t)(s_) * KV_STRIDE;               \
    uint32_t vst = sb + A_VB + (uint32_t)(s_) * KV_STRIDE;               \
    size_t roff = (size_t)(kt_) * 64 * DMOD;                             \
    for (int c = tid; c < 1024; c += 256) {                              \
        int r = c >> 4, o = c & 15;                                      \
        uint32_t d = (uint32_t)(r * 272 + o * 16);                       \
        size_t g = roff + (size_t)r * DMOD + o * 8;                      \
        cp16(kst + d, Kh + g);                                           \
        cp16(vst + d, Vh + g);                                           \
    }                                                                    \
} while (0)

    ISSUE_KV(kt0, 0);
    CP_COMMIT();
    ISSUE_KV(kt0 + 1, 1);
    CP_COMMIT();

    float* MX = (float*)(smc + A_MX);
    float* SU = (float*)(smc + A_SU);

    float rowm0 = -1e30f, rowm1 = -1e30f, rowl0 = 0.f, rowl1 = 0.f;

    float acc_o[8][4];
#pragma unroll
    for (int j = 0; j < 8; j++)
#pragma unroll
        for (int qq = 0; qq < 4; qq++) acc_o[j][qq] = 0.f;

    for (int kt = kt0; kt < 16; kt++) {
        const int p = (kt - kt0) & 1;
        if (kt == 15) { CP_WAIT(0); } else { CP_WAIT(1); }
        __syncthreads();                               // sync0: K/V stage ready

        const uint32_t kst = sb + A_KB + (uint32_t)p * KV_STRIDE;
        const uint32_t vst = sb + A_VB + (uint32_t)p * KV_STRIDE;

        // ---- S = Q * K^T (SCALE pre-folded into Q) ----
        float sacc[4][4];
#pragma unroll
        for (int j = 0; j < 4; j++)
#pragma unroll
            for (int qq = 0; qq < 4; qq++) sacc[j][qq] = 0.f;

#pragma unroll
        for (int ks = 0; ks < 8; ks++) {
            uint32_t ah[4];
            {
                uint32_t arow = (uint32_t)(wm + ((grp & 1) << 3) + li);
                uint32_t akb = (uint32_t)(ks * 32 + ((grp >> 1) << 4));
                LDMX4(ah, sb + A_QH + arow * 272 + akb);
            }
            uint32_t bh[2][4];
#pragma unroll
            for (int j2 = 0; j2 < 2; j2++) {
                uint32_t nrow = (uint32_t)(wnS + j2 * 16 + ((grp >> 1) << 3) + li);
                uint32_t kb = (uint32_t)(ks * 32 + ((grp & 1) << 4));
                LDMX4(bh[j2], kst + nrow * 272 + kb);
            }
#pragma unroll
            for (int j = 0; j < 4; j++)
                MMA_F16(sacc[j], ah, bh[j >> 1][(j & 1) * 2], bh[j >> 1][(j & 1) * 2 + 1]);
        }

        // ---- causal mask (additive only) ----
        {
            const int qg0 = qt * 64 + r0, qg1 = qg0 + 8;
#pragma unroll
            for (int j = 0; j < 4; j++) {
                int kg = kt * 64 + wnS + 8 * j + 2 * q;
                sacc[j][0] += (kg     <= qg0) ? -10000.f : 0.f;
                sacc[j][1] += (kg + 1 <= qg0) ? -10000.f : 0.f;
                sacc[j][2] += (kg     <= qg1) ? -10000.f : 0.f;
                sacc[j][3] += (kg + 1 <= qg1) ? -10000.f : 0.f;
            }
        }

        // ---- warp-local row max ----
        float m0 = fmaxf(fmaxf(sacc[0][0], sacc[0][1]), fmaxf(sacc[1][0], sacc[1][1]));
        m0 = fmaxf(m0, fmaxf(fmaxf(sacc[2][0], sacc[2][1]), fmaxf(sacc[3][0], sacc[3][1])));
        float m1 = fmaxf(fmaxf(sacc[0][2], sacc[0][3]), fmaxf(sacc[1][2], sacc[1][3]));
        m1 = fmaxf(m1, fmaxf(fmaxf(sacc[2][2], sacc[2][3]), fmaxf(sacc[3][2], sacc[3][3])));
        m0 = fmaxf(m0, __shfl_xor_sync(0xffffffffu, m0, 1));
        m0 = fmaxf(m0, __shfl_xor_sync(0xffffffffu, m0, 2));
        m1 = fmaxf(m1, __shfl_xor_sync(0xffffffffu, m1, 1));
        m1 = fmaxf(m1, __shfl_xor_sync(0xffffffffu, m1, 2));
        if (q == 0) { MX[cg * 64 + r0] = m0; MX[cg * 64 + r1] = m1; }
        __syncthreads();                               // sync1: maxes visible

        const float mn0 = fmaxf(rowm0, fmaxf(MX[r0], MX[64 + r0]));
        const float mn1 = fmaxf(rowm1, fmaxf(MX[r1], MX[64 + r1]));
        const float alpha0 = __expf(rowm0 - mn0);
        const float alpha1 = __expf(rowm1 - mn1);

        // ---- exp in fragments; own half as PV A-frags; write P to smem ----
        uint32_t pf[2][4];
        float s0 = 0.f, s1 = 0.f;
#pragma unroll
        for (int j = 0; j < 4; j++) {
            float p0 = __expf(sacc[j][0] - mn0);
            float p1 = __expf(sacc[j][1] - mn0);
            float p2 = __expf(sacc[j][2] - mn1);
            float p3 = __expf(sacc[j][3] - mn1);
            s0 += p0 + p1;
            s1 += p2 + p3;
            __half2 h01 = __floats2half2_rn(p0, p1);
            __half2 h23 = __floats2half2_rn(p2, p3);
            pf[j >> 1][((j & 1) << 1) + 0] = *(uint32_t*)&h01;
            pf[j >> 1][((j & 1) << 1) + 1] = *(uint32_t*)&h23;
            uint32_t cb = (uint32_t)((wnS + 8 * j + 2 * q) * 2);
            *(uint32_t*)(smc + A_PH + (size_t)r0 * 144 + cb) = *(uint32_t*)&h01;
            *(uint32_t*)(smc + A_PH + (size_t)r1 * 144 + cb) = *(uint32_t*)&h23;
        }
        s0 += __shfl_xor_sync(0xffffffffu, s0, 1);
        s0 += __shfl_xor_sync(0xffffffffu, s0, 2);
        s1 += __shfl_xor_sync(0xffffffffu, s1, 1);
        s1 += __shfl_xor_sync(0xffffffffu, s1, 2);
        if (q == 0) { SU[cg * 64 + r0] = s0; SU[cg * 64 + r1] = s1; }
        __syncthreads();                               // sync2: P + sums ready

        rowl0 = rowl0 * alpha0 + SU[r0] + SU[64 + r0];
        rowl1 = rowl1 * alpha1 + SU[r1] + SU[64 + r1];
        rowm0 = mn0;
        rowm1 = mn1;

        // ---- O = O*alpha + P * V ----
#pragma unroll
        for (int j = 0; j < 8; j++) {
            acc_o[j][0] *= alpha0; acc_o[j][1] *= alpha0;
            acc_o[j][2] *= alpha1; acc_o[j][3] *= alpha1;
        }
#pragma unroll
        for (int kc = 0; kc < 4; kc++) {
            uint32_t ph[4];
            if ((kc >> 1) == cg) {
                ph[0] = pf[kc & 1][0]; ph[1] = pf[kc & 1][1];
                ph[2] = pf[kc & 1][2]; ph[3] = pf[kc & 1][3];
            } else {
                uint32_t arow = (uint32_t)(wm + ((grp & 1) << 3) + li);
                uint32_t akb = (uint32_t)(kc * 32 + ((grp >> 1) << 4));
                LDMX4(ph, sb + A_PH + arow * 144 + akb);
            }
#pragma unroll
            for (int j2 = 0; j2 < 4; j2++) {
                uint32_t bvh[4];
                uint32_t krow = (uint32_t)(kc * 16 + ((grp & 1) << 3) + li);
                uint32_t nb = (uint32_t)((wnV + 16 * j2 + ((grp >> 1) << 3)) * 2);
                LDMX4T(bvh, vst + krow * 272 + nb);
#pragma unroll
                for (int jj = 0; jj < 2; jj++) {
                    int j = 2 * j2 + jj;
                    MMA_F16(acc_o[j], ph, bvh[jj * 2], bvh[jj * 2 + 1]);
                }
            }
        }
        __syncthreads();                               // sync3: stage consumed

        if (kt + 2 <= 15) {
            ISSUE_KV(kt + 2, p);
            CP_COMMIT();
        }
    }

    {
        const int grow0 = b * TSEQ + qt * 64 + r0;
        float scl0 = (1.f / rowl0) * mask[(size_t)b * TSEQ + qt * 64 + r0];
        float scl1 = (1.f / rowl1) * mask[(size_t)b * TSEQ + qt * 64 + r1];
#pragma unroll
        for (int j = 0; j < 8; j++) {
            int col = h * DH + wnV + j * 8 + 2 * q;
            float2 w0 = {acc_o[j][0] * scl0, acc_o[j][1] * scl0};
            float2 w1 = {acc_o[j][2] * scl1, acc_o[j][3] * scl1};
            *(float2*)&out[(size_t)grow0 * DMOD + col] = w0;
            *(float2*)&out[(size_t)(grow0 + 8) * DMOD + col] = w1;
        }
    }
}

extern "C" void kernel_launch(void* const* d_in, const int* in_sizes, int n_in,
                              void* d_out, int out_size) {
    const float* x    = (const float*)d_in[0];
    const float* mask = (const float*)d_in[1];
    const float* Wq   = (const float*)d_in[2];
    const float* Wk   = (const float*)d_in[3];
    const float* Wv   = (const float*)d_in[4];
    float* out = (float*)d_out;

    __half *xh, *wh, *qh, *kh, *vh;
    cudaGetSymbolAddress((void**)&xh, g_Xh);
    cudaGetSymbolAddress((void**)&wh, g_Wh);
    cudaGetSymbolAddress((void**)&qh, g_Qh);
    cudaGetSymbolAddress((void**)&kh, g_Kh);
    cudaGetSymbolAddress((void**)&vh, g_Vh);

    cudaFuncSetAttribute(gemm_qkv_f16, cudaFuncAttributeMaxDynamicSharedMemorySize,
                         GEMM_SMEM);
    cudaFuncSetAttribute(attn_tc, cudaFuncAttributeMaxDynamicSharedMemorySize,
                         ATTN_SMEM);

    cvt_all<<<8192 + 3 * 1024, 256>>>((const float4*)x, (const float4*)Wq,
                                      (const float4*)Wk, (const float4*)Wv,
                                      (uint2*)xh, (uint2*)wh);

    dim3 ggrid(3 * DMOD / 128, (BATCH * TSEQ) / 128);
    gemm_qkv_f16<<<ggrid, 256, GEMM_SMEM>>>(xh, wh, qh, kh, vh);

    dim3 agrid(TSEQ / 64, NH, BATCH);
    attn_tc<<<agrid, 256, ATTN_SMEM>>>(mask, out);
}

// round 14
// speedup vs baseline: 1.0738x; 1.0347x over previous
#include <cuda_runtime.h>
#include <cuda_bf16.h>
#include <cuda_fp16.h>
#include <cstdint>

#define BATCH 8
#define TSEQ 1024
#define DMOD 1024
#define NH 8
#define DH 128
#define SCALE 0.08838834764831845f

__device__ __half g_Xh[BATCH * TSEQ * DMOD];
__device__ __half g_Wh[3 * DMOD * DMOD];
__device__ __half g_Qh[BATCH * TSEQ * DMOD];
__device__ __half g_Kh[BATCH * TSEQ * DMOD];
__device__ __half g_Vh[BATCH * TSEQ * DMOD];

__device__ __forceinline__ uint32_t smem_u32(const void* p) {
    uint32_t a;
    asm("{ .reg .u64 t; cvta.to.shared.u64 t, %1; cvt.u32.u64 %0, t; }"
        : "=r"(a) : "l"(p));
    return a;
}
__device__ __forceinline__ void cp16(uint32_t dst, const void* src) {
    asm volatile("cp.async.cg.shared.global [%0], [%1], 16;"
                 :: "r"(dst), "l"(src) : "memory");
}
#define CP_COMMIT() asm volatile("cp.async.commit_group;" ::: "memory")
#define CP_WAIT(n)  asm volatile("cp.async.wait_group %0;" :: "n"(n) : "memory")

#define MMA_F16(c, a, b0_, b1_) \
    asm volatile("mma.sync.aligned.m16n8k16.row.col.f32.f16.f16.f32 " \
                 "{%0,%1,%2,%3}, {%4,%5,%6,%7}, {%8,%9}, {%0,%1,%2,%3};" \
                 : "+f"((c)[0]), "+f"((c)[1]), "+f"((c)[2]), "+f"((c)[3]) \
                 : "r"((a)[0]), "r"((a)[1]), "r"((a)[2]), "r"((a)[3]), \
                   "r"(b0_), "r"(b1_))

#define LDMX4(r, addr) \
    asm volatile("ldmatrix.sync.aligned.m8n8.x4.shared.b16 {%0,%1,%2,%3}, [%4];" \
                 : "=r"((r)[0]), "=r"((r)[1]), "=r"((r)[2]), "=r"((r)[3]) : "r"(addr))
#define LDMX4T(r, addr) \
    asm volatile("ldmatrix.sync.aligned.m8n8.x4.trans.shared.b16 {%0,%1,%2,%3}, [%4];" \
                 : "=r"((r)[0]), "=r"((r)[1]), "=r"((r)[2]), "=r"((r)[3]) : "r"(addr))

#define BAR_G(gid) \
    asm volatile("bar.sync %0, 128;" :: "r"((gid) + 1) : "memory")

// ===========================================================================
// Fused conversion: X (8192 blocks) then Wq/Wk/Wv (1024 each).
// ===========================================================================
__global__ __launch_bounds__(256) void cvt_all(const float4* __restrict__ x,
                                               const float4* __restrict__ w0,
                                               const float4* __restrict__ w1,
                                               const float4* __restrict__ w2,
                                               uint2* __restrict__ xh,
                                               uint2* __restrict__ wh) {
    int bi = blockIdx.x;
    const float4* src;
    uint2* dst;
    int i;
    if (bi < 8192) {
        i = bi * 256 + threadIdx.x;
        src = x;
        dst = xh;
    } else {
        int wsel = (bi - 8192) >> 10;
        i = ((bi - 8192) & 1023) * 256 + threadIdx.x;
        src = (wsel == 0) ? w0 : (wsel == 1) ? w1 : w2;
        dst = wh + (size_t)wsel * (DMOD * DMOD / 4);
    }
    float4 v = src[i];
    __half2 p01 = __floats2half2_rn(v.x, v.y);
    __half2 p23 = __floats2half2_rn(v.z, v.w);
    uint2 H;
    H.x = *(uint32_t*)&p01;
    H.y = *(uint32_t*)&p23;
    dst[i] = H;
}

// ===========================================================================
// Fused QKV GEMM (at mma.sync floor). SCALE folded into Q epilogue.
// ===========================================================================
#define GTILE 10240
#define GSTAGE (2 * GTILE)
#define GEMM_SMEM (2 * GSTAGE)

__global__ __launch_bounds__(256, 2) void gemm_qkv_f16(
    const __half* __restrict__ Xh, const __half* __restrict__ Wh,
    __half* __restrict__ qh, __half* __restrict__ kh, __half* __restrict__ vh) {
    extern __shared__ char smc[];
    const uint32_t sb = smem_u32(smc);

    const int tid = threadIdx.x;
    const int lane = tid & 31, wid = tid >> 5;
    const int bm = blockIdx.y << 7;
    const int bnG = blockIdx.x << 7;
    const int wm = (wid & 1) * 64, wn = (wid >> 1) * 32;
    const int fm = lane >> 2;
    const int fkb = (lane & 3) * 4;
    const int grp = lane >> 3, li = lane & 7;

    float acc[4][4][4];
#pragma unroll
    for (int i = 0; i < 4; i++)
#pragma unroll
        for (int j = 0; j < 4; j++)
#pragma unroll
            for (int q = 0; q < 4; q++) acc[i][j][q] = 0.f;

    const int c0row = tid >> 2;
    const int c1row = c0row + 64;
    const int ce = (tid & 3) * 8;
    const uint32_t d0 = (uint32_t)(c0row * 80 + (tid & 3) * 16);
    const uint32_t d1 = (uint32_t)(c1row * 80 + (tid & 3) * 16);

#define ISSUE_STAGE(kt, p) do {                                        \
    uint32_t s0 = sb + (p) * GSTAGE;                                   \
    size_t a0 = (size_t)(bm + c0row) * 1024 + (size_t)(kt) * 32 + ce;  \
    size_t a1 = (size_t)(bm + c1row) * 1024 + (size_t)(kt) * 32 + ce;  \
    size_t b0 = (size_t)(bnG + c0row) * 1024 + (size_t)(kt) * 32 + ce; \
    size_t b1 = (size_t)(bnG + c1row) * 1024 + (size_t)(kt) * 32 + ce; \
    cp16(s0 + d0,         Xh + a0);  cp16(s0 + d1,         Xh + a1);   \
    cp16(s0 + GTILE + d0, Wh + b0);  cp16(s0 + GTILE + d1, Wh + b1);   \
    CP_COMMIT();                                                       \
} while (0)

    ISSUE_STAGE(0, 0);

    for (int kt = 0; kt < 32; kt++) {
        const int p = kt & 1;
        if (kt < 31) {
            ISSUE_STAGE(kt + 1, p ^ 1);
            CP_WAIT(1);
        } else {
            CP_WAIT(0);
        }
        __syncthreads();

        const uint32_t st = sb + p * GSTAGE;
#pragma unroll
        for (int k16o = 0; k16o < 64; k16o += 32) {
            uint32_t ah[4][4], bh[2][4];
            const uint32_t akb = (uint32_t)(k16o + ((grp >> 1) << 4));
            const uint32_t bkb = (uint32_t)(k16o + ((grp & 1) << 4));
#pragma unroll
            for (int np = 0; np < 2; np++) {
                uint32_t nrow = (uint32_t)(wn + np * 16 + ((grp >> 1) << 3) + li);
                LDMX4(bh[np], st + GTILE + nrow * 80 + bkb);
            }
#pragma unroll
            for (int mt = 0; mt < 4; mt++) {
                uint32_t arow = (uint32_t)(wm + mt * 16 + ((grp & 1) << 3) + li);
                LDMX4(ah[mt], st + arow * 80 + akb);
            }
#pragma unroll
            for (int mt = 0; mt < 4; mt++)
#pragma unroll
                for (int nt = 0; nt < 4; nt++)
                    MMA_F16(acc[mt][nt], ah[mt], bh[nt >> 1][(nt & 1) * 2],
                            bh[nt >> 1][(nt & 1) * 2 + 1]);
        }
        __syncthreads();
    }

    const int which = bnG >> 10;
    const int nloc = bnG & 1023;
    __half* C = (which == 0) ? qh : (which == 1) ? kh : vh;
    const float escl = (which == 0) ? SCALE : 1.f;

#pragma unroll
    for (int mt = 0; mt < 4; mt++) {
        size_t m0 = (size_t)(bm + wm + mt * 16 + fm);
#pragma unroll
        for (int nt = 0; nt < 4; nt++) {
            size_t n0 = (size_t)(nloc + wn + nt * 8 + (fkb >> 1));
            __half2 p01 = __floats2half2_rn(acc[mt][nt][0] * escl, acc[mt][nt][1] * escl);
            __half2 p23 = __floats2half2_rn(acc[mt][nt][2] * escl, acc[mt][nt][3] * escl);
            *(uint32_t*)((char*)C + (m0 * 1024 + n0) * 2) = *(uint32_t*)&p01;
            *(uint32_t*)((char*)C + ((m0 + 8) * 1024 + n0) * 2) = *(uint32_t*)&p23;
        }
    }
}

// ===========================================================================
// Flash attention, split-KV two-group design.
// Warp tile: 16 q-rows x full 64 k-cols (softmax fully warp-local).
// Group g (warps 4g..4g+3) processes tiles kt0+g, kt0+g+2, ... with its own
// stages, running stats, and O; merged exactly at the end.
// ===========================================================================
#define A_QH 0
#define A_ST 17408
#define ST_SZ 34816                 // K 17408 + V 17408
#define ATTN_SMEM (17408 + 4 * 34816)   // 156672

__global__ __launch_bounds__(256, 1) void attn_tc(const float* __restrict__ mask,
                                                  float* __restrict__ out) {
    extern __shared__ char smc[];
    const uint32_t sb = smem_u32(smc);

    const int tid = threadIdx.x;
    const int lane = tid & 31, wid = tid >> 5;
    const int qt = (blockIdx.x == 0) ? 15 : (int)blockIdx.x - 1;
    const int h = blockIdx.y, b = blockIdx.z;
    const int g = wid >> 2, wg = wid & 3;
    const int wm = wg * 16;
    const int fm = lane >> 2, q = lane & 3;
    const int grp = lane >> 3, li = lane & 7;
    const int r0 = wm + fm, r1 = r0 + 8;
    const int gtid = tid & 127;

    const size_t bh_off = (size_t)b * TSEQ * DMOD + (size_t)h * DH;
    const __half* Qh = g_Qh + bh_off;
    const __half* Kh = g_Kh + bh_off;
    const __half* Vh = g_Vh + bh_off;

    const int kt0 = (qt == 15) ? 0 : qt;
    const int total = 16 - kt0;
    const int n = (g == 0) ? ((total + 1) >> 1) : (total >> 1);  // >=1 always

    // Q tile (all 256 threads), commit group 0
    for (int c = tid; c < 1024; c += 256) {
        int r = c >> 4, o = c & 15;
        cp16(sb + A_QH + (uint32_t)(r * 272 + o * 16),
             Qh + (size_t)(qt * 64 + r) * DMOD + o * 8);
    }
    CP_COMMIT();

#define ISSUE_KV_G(kt_, s_) do {                                         \
    uint32_t kst = sb + A_ST + (uint32_t)(g * 2 + (s_)) * ST_SZ;         \
    size_t roff = (size_t)(kt_) * 64 * DMOD;                             \
    for (int c = gtid; c < 1024; c += 128) {                             \
        int r = c >> 4, o = c & 15;                                      \
        uint32_t d = (uint32_t)(r * 272 + o * 16);                       \
        size_t gaddr = roff + (size_t)r * DMOD + o * 8;                  \
        cp16(kst + d,         Kh + gaddr);                               \
        cp16(kst + 17408 + d, Vh + gaddr);                               \
    }                                                                    \
} while (0)

    ISSUE_KV_G(kt0 + g, 0);
    CP_COMMIT();
    if (n > 1) ISSUE_KV_G(kt0 + g + 2, 1);
    CP_COMMIT();

    CP_WAIT(2);                // Q group complete
    __syncthreads();

    // Persistent Q fragments (SCALE pre-folded)
    uint32_t Qf[8][4];
    {
        uint32_t arow = (uint32_t)(wm + ((grp & 1) << 3) + li);
#pragma unroll
        for (int ks = 0; ks < 8; ks++) {
            uint32_t akb = (uint32_t)(ks * 32 + ((grp >> 1) << 4));
            LDMX4(Qf[ks], sb + A_QH + arow * 272 + akb);
        }
    }

    float rowm0 = -1e30f, rowm1 = -1e30f, rowl0 = 0.f, rowl1 = 0.f;
    float acc_o[16][4];
#pragma unroll
    for (int j = 0; j < 16; j++)
#pragma unroll
        for (int qq = 0; qq < 4; qq++) acc_o[j][qq] = 0.f;

    for (int i = 0; i < n; i++) {
        const int kt = kt0 + g + 2 * i;
        const uint32_t kstg = sb + A_ST + (uint32_t)(g * 2 + (i & 1)) * ST_SZ;
        const uint32_t vstg = kstg + 17408;

        if (i == n - 1) { CP_WAIT(0); } else { CP_WAIT(1); }
        BAR_G(g);                          // stage ready for this group

        // ---- S (16x64) = Q * K^T ----
        float sacc[8][4];
#pragma unroll
        for (int j = 0; j < 8; j++)
#pragma unroll
            for (int qq = 0; qq < 4; qq++) sacc[j][qq] = 0.f;

#pragma unroll
        for (int ks = 0; ks < 8; ks++) {
            uint32_t bh[4][4];
            uint32_t kb = (uint32_t)(ks * 32 + ((grp & 1) << 4));
#pragma unroll
            for (int nf = 0; nf < 4; nf++) {
                uint32_t nrow = (uint32_t)(nf * 16 + ((grp >> 1) << 3) + li);
                LDMX4(bh[nf], kstg + nrow * 272 + kb);
            }
#pragma unroll
            for (int nf = 0; nf < 4; nf++) {
                MMA_F16(sacc[2 * nf],     Qf[ks], bh[nf][0], bh[nf][1]);
                MMA_F16(sacc[2 * nf + 1], Qf[ks], bh[nf][2], bh[nf][3]);
            }
        }

        // ---- causal mask ----
        {
            const int qg0 = qt * 64 + r0, qg1 = qg0 + 8;
#pragma unroll
            for (int nf = 0; nf < 8; nf++) {
                int kg = kt * 64 + nf * 8 + 2 * q;
                sacc[nf][0] += (kg     <= qg0) ? -10000.f : 0.f;
                sacc[nf][1] += (kg + 1 <= qg0) ? -10000.f : 0.f;
                sacc[nf][2] += (kg     <= qg1) ? -10000.f : 0.f;
                sacc[nf][3] += (kg + 1 <= qg1) ? -10000.f : 0.f;
            }
        }

        // ---- warp-local full-row softmax ----
        float m0 = fmaxf(sacc[0][0], sacc[0][1]);
        float m1 = fmaxf(sacc[0][2], sacc[0][3]);
#pragma unroll
        for (int nf = 1; nf < 8; nf++) {
            m0 = fmaxf(m0, fmaxf(sacc[nf][0], sacc[nf][1]));
            m1 = fmaxf(m1, fmaxf(sacc[nf][2], sacc[nf][3]));
        }
        m0 = fmaxf(m0, __shfl_xor_sync(0xffffffffu, m0, 1));
        m0 = fmaxf(m0, __shfl_xor_sync(0xffffffffu, m0, 2));
        m1 = fmaxf(m1, __shfl_xor_sync(0xffffffffu, m1, 1));
        m1 = fmaxf(m1, __shfl_xor_sync(0xffffffffu, m1, 2));

        const float mn0 = fmaxf(rowm0, m0);
        const float mn1 = fmaxf(rowm1, m1);
        const float alpha0 = __expf(rowm0 - mn0);
        const float alpha1 = __expf(rowm1 - mn1);

        uint32_t pf[4][4];
        float s0 = 0.f, s1 = 0.f;
#pragma unroll
        for (int nf = 0; nf < 8; nf++) {
            float p0 = __expf(sacc[nf][0] - mn0);
            float p1 = __expf(sacc[nf][1] - mn0);
            float p2 = __expf(sacc[nf][2] - mn1);
            float p3 = __expf(sacc[nf][3] - mn1);
            s0 += p0 + p1;
            s1 += p2 + p3;
            __half2 h01 = __floats2half2_rn(p0, p1);
            __half2 h23 = __floats2half2_rn(p2, p3);
            pf[nf >> 1][((nf & 1) << 1) + 0] = *(uint32_t*)&h01;
            pf[nf >> 1][((nf & 1) << 1) + 1] = *(uint32_t*)&h23;
        }
        s0 += __shfl_xor_sync(0xffffffffu, s0, 1);
        s0 += __shfl_xor_sync(0xffffffffu, s0, 2);
        s1 += __shfl_xor_sync(0xffffffffu, s1, 1);
        s1 += __shfl_xor_sync(0xffffffffu, s1, 2);
        rowl0 = rowl0 * alpha0 + s0;
        rowl1 = rowl1 * alpha1 + s1;
        rowm0 = mn0;
        rowm1 = mn1;

#pragma unroll
        for (int j = 0; j < 16; j++) {
            acc_o[j][0] *= alpha0; acc_o[j][1] *= alpha0;
            acc_o[j][2] *= alpha1; acc_o[j][3] *= alpha1;
        }

        // ---- O (16x128) += P * V ----
#pragma unroll
        for (int kc = 0; kc < 4; kc++) {
            uint32_t krow = (uint32_t)(kc * 16 + ((grp & 1) << 3) + li);
#pragma unroll
            for (int nf2 = 0; nf2 < 8; nf2++) {
                uint32_t bvh[4];
                uint32_t nb = (uint32_t)((nf2 * 16 + ((grp >> 1) << 3)) * 2);
                LDMX4T(bvh, vstg + krow * 272 + nb);
                MMA_F16(acc_o[2 * nf2],     pf[kc], bvh[0], bvh[1]);
                MMA_F16(acc_o[2 * nf2 + 1], pf[kc], bvh[2], bvh[3]);
            }
        }
        BAR_G(g);                          // stage consumed

        if (i + 2 < n) ISSUE_KV_G(kt0 + g + 2 * (i + 2), i & 1);
        CP_COMMIT();
    }

    // ---- merge the two groups (exact split-KV combine) ----
    float* Ored = (float*)(smc + A_ST + 2 * ST_SZ);   // group 1's stage 0
    float* Mst = Ored + 64 * 128;
    float* Lst = Mst + 64;
    if (g == 1) {
#pragma unroll
        for (int nf = 0; nf < 16; nf++) {
            int col = nf * 8 + 2 * q;
            *(float2*)&Ored[r0 * 128 + col] = make_float2(acc_o[nf][0], acc_o[nf][1]);
            *(float2*)&Ored[r1 * 128 + col] = make_float2(acc_o[nf][2], acc_o[nf][3]);
        }
        if (q == 0) {
            Mst[r0] = rowm0; Lst[r0] = rowl0;
            Mst[r1] = rowm1; Lst[r1] = rowl1;
        }
    }
    __syncthreads();
    if (g == 0) {
        const float mB0 = Mst[r0], lB0 = Lst[r0];
        const float mB1 = Mst[r1], lB1 = Lst[r1];
        const float mm0 = fmaxf(rowm0, mB0), mm1 = fmaxf(rowm1, mB1);
        const float fa0 = __expf(rowm0 - mm0), fb0 = __expf(mB0 - mm0);
        const float fa1 = __expf(rowm1 - mm1), fb1 = __expf(mB1 - mm1);
        const float l0 = rowl0 * fa0 + lB0 * fb0;
        const float l1 = rowl1 * fa1 + lB1 * fb1;
        const int grow0 = b * TSEQ + qt * 64 + r0;
        const float scl0 = (1.f / l0) * mask[(size_t)b * TSEQ + qt * 64 + r0];
        const float scl1 = (1.f / l1) * mask[(size_t)b * TSEQ + qt * 64 + r1];
#pragma unroll
        for (int nf = 0; nf < 16; nf++) {
            int col = nf * 8 + 2 * q;
            float2 pr0 = *(float2*)&Ored[r0 * 128 + col];
            float2 pr1 = *(float2*)&Ored[r1 * 128 + col];
            float2 w0 = make_float2((acc_o[nf][0] * fa0 + pr0.x * fb0) * scl0,
                                    (acc_o[nf][1] * fa0 + pr0.y * fb0) * scl0);
            float2 w1 = make_float2((acc_o[nf][2] * fa1 + pr1.x * fb1) * scl1,
                                    (acc_o[nf][3] * fa1 + pr1.y * fb1) * scl1);
            *(float2*)&out[(size_t)grow0 * DMOD + h * DH + col] = w0;
            *(float2*)&out[(size_t)(grow0 + 8) * DMOD + h * DH + col] = w1;
        }
    }
}

extern "C" void kernel_launch(void* const* d_in, const int* in_sizes, int n_in,
                              void* d_out, int out_size) {
    const float* x    = (const float*)d_in[0];
    const float* mask = (const float*)d_in[1];
    const float* Wq   = (const float*)d_in[2];
    const float* Wk   = (const float*)d_in[3];
    const float* Wv   = (const float*)d_in[4];
    float* out = (float*)d_out;

    __half *xh, *wh, *qh, *kh, *vh;
    cudaGetSymbolAddress((void**)&xh, g_Xh);
    cudaGetSymbolAddress((void**)&wh, g_Wh);
    cudaGetSymbolAddress((void**)&qh, g_Qh);
    cudaGetSymbolAddress((void**)&kh, g_Kh);
    cudaGetSymbolAddress((void**)&vh, g_Vh);

    cudaFuncSetAttribute(gemm_qkv_f16, cudaFuncAttributeMaxDynamicSharedMemorySize,
                         GEMM_SMEM);
    cudaFuncSetAttribute(attn_tc, cudaFuncAttributeMaxDynamicSharedMemorySize,
                         ATTN_SMEM);

    cvt_all<<<8192 + 3 * 1024, 256>>>((const float4*)x, (const float4*)Wq,
                                      (const float4*)Wk, (const float4*)Wv,
                                      (uint2*)xh, (uint2*)wh);

    dim3 ggrid(3 * DMOD / 128, (BATCH * TSEQ) / 128);
    gemm_qkv_f16<<<ggrid, 256, GEMM_SMEM>>>(xh, wh, qh, kh, vh);

    dim3 agrid(TSEQ / 64, NH, BATCH);
    attn_tc<<<agrid, 256, ATTN_SMEM>>>(mask, out);
}

// round 15
// speedup vs baseline: 1.0749x; 1.0010x over previous
#include <cuda_runtime.h>
#include <cuda_bf16.h>
#include <cuda_fp16.h>
#include <cstdint>

#define BATCH 8
#define TSEQ 1024
#define DMOD 1024
#define NH 8
#define DH 128
#define SCALE 0.08838834764831845f
#define LOG2E 1.4426950408889634f
#define MASKV (-10000.0f * LOG2E)

__device__ __half g_Xh[BATCH * TSEQ * DMOD];
__device__ __half g_Wh[3 * DMOD * DMOD];
__device__ __half g_Qh[BATCH * TSEQ * DMOD];
__device__ __half g_Kh[BATCH * TSEQ * DMOD];
__device__ __half g_Vh[BATCH * TSEQ * DMOD];

__device__ __forceinline__ uint32_t smem_u32(const void* p) {
    uint32_t a;
    asm("{ .reg .u64 t; cvta.to.shared.u64 t, %1; cvt.u32.u64 %0, t; }"
        : "=r"(a) : "l"(p));
    return a;
}
__device__ __forceinline__ void cp16(uint32_t dst, const void* src) {
    asm volatile("cp.async.cg.shared.global [%0], [%1], 16;"
                 :: "r"(dst), "l"(src) : "memory");
}
#define CP_COMMIT() asm volatile("cp.async.commit_group;" ::: "memory")
#define CP_WAIT(n)  asm volatile("cp.async.wait_group %0;" :: "n"(n) : "memory")

#define MMA_F16(c, a, b0_, b1_) \
    asm volatile("mma.sync.aligned.m16n8k16.row.col.f32.f16.f16.f32 " \
                 "{%0,%1,%2,%3}, {%4,%5,%6,%7}, {%8,%9}, {%0,%1,%2,%3};" \
                 : "+f"((c)[0]), "+f"((c)[1]), "+f"((c)[2]), "+f"((c)[3]) \
                 : "r"((a)[0]), "r"((a)[1]), "r"((a)[2]), "r"((a)[3]), \
                   "r"(b0_), "r"(b1_))

#define LDMX4(r, addr) \
    asm volatile("ldmatrix.sync.aligned.m8n8.x4.shared.b16 {%0,%1,%2,%3}, [%4];" \
                 : "=r"((r)[0]), "=r"((r)[1]), "=r"((r)[2]), "=r"((r)[3]) : "r"(addr))
#define LDMX4T(r, addr) \
    asm volatile("ldmatrix.sync.aligned.m8n8.x4.trans.shared.b16 {%0,%1,%2,%3}, [%4];" \
                 : "=r"((r)[0]), "=r"((r)[1]), "=r"((r)[2]), "=r"((r)[3]) : "r"(addr))

#define BAR_G(gid) \
    asm volatile("bar.sync %0, 128;" :: "r"((gid) + 1) : "memory")

#define EX2_F16X2(d, a) \
    asm("ex2.approx.f16x2 %0, %1;" : "=r"(d) : "r"(a))

// ===========================================================================
// Fused conversion: X (8192 blocks) then Wq/Wk/Wv (1024 each).
// ===========================================================================
__global__ __launch_bounds__(256) void cvt_all(const float4* __restrict__ x,
                                               const float4* __restrict__ w0,
                                               const float4* __restrict__ w1,
                                               const float4* __restrict__ w2,
                                               uint2* __restrict__ xh,
                                               uint2* __restrict__ wh) {
    int bi = blockIdx.x;
    const float4* src;
    uint2* dst;
    int i;
    if (bi < 8192) {
        i = bi * 256 + threadIdx.x;
        src = x;
        dst = xh;
    } else {
        int wsel = (bi - 8192) >> 10;
        i = ((bi - 8192) & 1023) * 256 + threadIdx.x;
        src = (wsel == 0) ? w0 : (wsel == 1) ? w1 : w2;
        dst = wh + (size_t)wsel * (DMOD * DMOD / 4);
    }
    float4 v = src[i];
    __half2 p01 = __floats2half2_rn(v.x, v.y);
    __half2 p23 = __floats2half2_rn(v.z, v.w);
    uint2 H;
    H.x = *(uint32_t*)&p01;
    H.y = *(uint32_t*)&p23;
    dst[i] = H;
}

// ===========================================================================
// Fused QKV GEMM (at mma.sync floor). SCALE*log2e folded into Q epilogue.
// ===========================================================================
#define GTILE 10240
#define GSTAGE (2 * GTILE)
#define GEMM_SMEM (2 * GSTAGE)

__global__ __launch_bounds__(256, 2) void gemm_qkv_f16(
    const __half* __restrict__ Xh, const __half* __restrict__ Wh,
    __half* __restrict__ qh, __half* __restrict__ kh, __half* __restrict__ vh) {
    extern __shared__ char smc[];
    const uint32_t sb = smem_u32(smc);

    const int tid = threadIdx.x;
    const int lane = tid & 31, wid = tid >> 5;
    const int bm = blockIdx.y << 7;
    const int bnG = blockIdx.x << 7;
    const int wm = (wid & 1) * 64, wn = (wid >> 1) * 32;
    const int fm = lane >> 2;
    const int fkb = (lane & 3) * 4;
    const int grp = lane >> 3, li = lane & 7;

    float acc[4][4][4];
#pragma unroll
    for (int i = 0; i < 4; i++)
#pragma unroll
        for (int j = 0; j < 4; j++)
#pragma unroll
            for (int q = 0; q < 4; q++) acc[i][j][q] = 0.f;

    const int c0row = tid >> 2;
    const int c1row = c0row + 64;
    const int ce = (tid & 3) * 8;
    const uint32_t d0 = (uint32_t)(c0row * 80 + (tid & 3) * 16);
    const uint32_t d1 = (uint32_t)(c1row * 80 + (tid & 3) * 16);

#define ISSUE_STAGE(kt, p) do {                                        \
    uint32_t s0 = sb + (p) * GSTAGE;                                   \
    size_t a0 = (size_t)(bm + c0row) * 1024 + (size_t)(kt) * 32 + ce;  \
    size_t a1 = (size_t)(bm + c1row) * 1024 + (size_t)(kt) * 32 + ce;  \
    size_t b0 = (size_t)(bnG + c0row) * 1024 + (size_t)(kt) * 32 + ce; \
    size_t b1 = (size_t)(bnG + c1row) * 1024 + (size_t)(kt) * 32 + ce; \
    cp16(s0 + d0,         Xh + a0);  cp16(s0 + d1,         Xh + a1);   \
    cp16(s0 + GTILE + d0, Wh + b0);  cp16(s0 + GTILE + d1, Wh + b1);   \
    CP_COMMIT();                                                       \
} while (0)

    ISSUE_STAGE(0, 0);

    for (int kt = 0; kt < 32; kt++) {
        const int p = kt & 1;
        if (kt < 31) {
            ISSUE_STAGE(kt + 1, p ^ 1);
            CP_WAIT(1);
        } else {
            CP_WAIT(0);
        }
        __syncthreads();

        const uint32_t st = sb + p * GSTAGE;
#pragma unroll
        for (int k16o = 0; k16o < 64; k16o += 32) {
            uint32_t ah[4][4], bh[2][4];
            const uint32_t akb = (uint32_t)(k16o + ((grp >> 1) << 4));
            const uint32_t bkb = (uint32_t)(k16o + ((grp & 1) << 4));
#pragma unroll
            for (int np = 0; np < 2; np++) {
                uint32_t nrow = (uint32_t)(wn + np * 16 + ((grp >> 1) << 3) + li);
                LDMX4(bh[np], st + GTILE + nrow * 80 + bkb);
            }
#pragma unroll
            for (int mt = 0; mt < 4; mt++) {
                uint32_t arow = (uint32_t)(wm + mt * 16 + ((grp & 1) << 3) + li);
                LDMX4(ah[mt], st + arow * 80 + akb);
            }
#pragma unroll
            for (int mt = 0; mt < 4; mt++)
#pragma unroll
                for (int nt = 0; nt < 4; nt++)
                    MMA_F16(acc[mt][nt], ah[mt], bh[nt >> 1][(nt & 1) * 2],
                            bh[nt >> 1][(nt & 1) * 2 + 1]);
        }
        __syncthreads();
    }

    const int which = bnG >> 10;
    const int nloc = bnG & 1023;
    __half* C = (which == 0) ? qh : (which == 1) ? kh : vh;
    const float escl = (which == 0) ? (SCALE * LOG2E) : 1.f;

#pragma unroll
    for (int mt = 0; mt < 4; mt++) {
        size_t m0 = (size_t)(bm + wm + mt * 16 + fm);
#pragma unroll
        for (int nt = 0; nt < 4; nt++) {
            size_t n0 = (size_t)(nloc + wn + nt * 8 + (fkb >> 1));
            __half2 p01 = __floats2half2_rn(acc[mt][nt][0] * escl, acc[mt][nt][1] * escl);
            __half2 p23 = __floats2half2_rn(acc[mt][nt][2] * escl, acc[mt][nt][3] * escl);
            *(uint32_t*)((char*)C + (m0 * 1024 + n0) * 2) = *(uint32_t*)&p01;
            *(uint32_t*)((char*)C + ((m0 + 8) * 1024 + n0) * 2) = *(uint32_t*)&p23;
        }
    }
}

// ===========================================================================
// Flash attention, split-KV two-group, log2-domain softmax with ex2.f16x2.
// ===========================================================================
#define A_QH 0
#define A_ST 17408
#define ST_SZ 34816
#define ATTN_SMEM (17408 + 4 * 34816)

__global__ __launch_bounds__(256, 1) void attn_tc(const float* __restrict__ mask,
                                                  float* __restrict__ out) {
    extern __shared__ char smc[];
    const uint32_t sb = smem_u32(smc);

    const int tid = threadIdx.x;
    const int lane = tid & 31, wid = tid >> 5;
    const int qt = (blockIdx.x == 0) ? 15 : (int)blockIdx.x - 1;
    const int h = blockIdx.y, b = blockIdx.z;
    const int g = wid >> 2, wg = wid & 3;
    const int wm = wg * 16;
    const int fm = lane >> 2, q = lane & 3;
    const int grp = lane >> 3, li = lane & 7;
    const int r0 = wm + fm, r1 = r0 + 8;
    const int gtid = tid & 127;

    const size_t bh_off = (size_t)b * TSEQ * DMOD + (size_t)h * DH;
    const __half* Qh = g_Qh + bh_off;
    const __half* Kh = g_Kh + bh_off;
    const __half* Vh = g_Vh + bh_off;

    const int kt0 = (qt == 15) ? 0 : qt;
    const int total = 16 - kt0;
    const int n = (g == 0) ? ((total + 1) >> 1) : (total >> 1);

    for (int c = tid; c < 1024; c += 256) {
        int r = c >> 4, o = c & 15;
        cp16(sb + A_QH + (uint32_t)(r * 272 + o * 16),
             Qh + (size_t)(qt * 64 + r) * DMOD + o * 8);
    }
    CP_COMMIT();

#define ISSUE_KV_G(kt_, s_) do {                                         \
    uint32_t kst = sb + A_ST + (uint32_t)(g * 2 + (s_)) * ST_SZ;         \
    size_t roff = (size_t)(kt_) * 64 * DMOD;                             \
    for (int c = gtid; c < 1024; c += 128) {                             \
        int r = c >> 4, o = c & 15;                                      \
        uint32_t d = (uint32_t)(r * 272 + o * 16);                       \
        size_t gaddr = roff + (size_t)r * DMOD + o * 8;                  \
        cp16(kst + d,         Kh + gaddr);                               \
        cp16(kst + 17408 + d, Vh + gaddr);                               \
    }                                                                    \
} while (0)

    ISSUE_KV_G(kt0 + g, 0);
    CP_COMMIT();
    if (n > 1) ISSUE_KV_G(kt0 + g + 2, 1);
    CP_COMMIT();

    CP_WAIT(2);
    __syncthreads();

    uint32_t Qf[8][4];
    {
        uint32_t arow = (uint32_t)(wm + ((grp & 1) << 3) + li);
#pragma unroll
        for (int ks = 0; ks < 8; ks++) {
            uint32_t akb = (uint32_t)(ks * 32 + ((grp >> 1) << 4));
            LDMX4(Qf[ks], sb + A_QH + arow * 272 + akb);
        }
    }

    float rowm0 = -1e30f, rowm1 = -1e30f, rowl0 = 0.f, rowl1 = 0.f;
    float acc_o[16][4];
#pragma unroll
    for (int j = 0; j < 16; j++)
#pragma unroll
        for (int qq = 0; qq < 4; qq++) acc_o[j][qq] = 0.f;

    for (int i = 0; i < n; i++) {
        const int kt = kt0 + g + 2 * i;
        const uint32_t kstg = sb + A_ST + (uint32_t)(g * 2 + (i & 1)) * ST_SZ;
        const uint32_t vstg = kstg + 17408;

        if (i == n - 1) { CP_WAIT(0); } else { CP_WAIT(1); }
        BAR_G(g);

        // ---- S (16x64) = Q * K^T  (log2 units) ----
        float sacc[8][4];
#pragma unroll
        for (int j = 0; j < 8; j++)
#pragma unroll
            for (int qq = 0; qq < 4; qq++) sacc[j][qq] = 0.f;

#pragma unroll
        for (int ks = 0; ks < 8; ks++) {
            uint32_t bh[4][4];
            uint32_t kb = (uint32_t)(ks * 32 + ((grp & 1) << 4));
#pragma unroll
            for (int nf = 0; nf < 4; nf++) {
                uint32_t nrow = (uint32_t)(nf * 16 + ((grp >> 1) << 3) + li);
                LDMX4(bh[nf], kstg + nrow * 272 + kb);
            }
#pragma unroll
            for (int nf = 0; nf < 4; nf++) {
                MMA_F16(sacc[2 * nf],     Qf[ks], bh[nf][0], bh[nf][1]);
                MMA_F16(sacc[2 * nf + 1], Qf[ks], bh[nf][2], bh[nf][3]);
            }
        }

        // ---- causal mask (log2 units) ----
        {
            const int qg0 = qt * 64 + r0, qg1 = qg0 + 8;
#pragma unroll
            for (int nf = 0; nf < 8; nf++) {
                int kg = kt * 64 + nf * 8 + 2 * q;
                sacc[nf][0] += (kg     <= qg0) ? MASKV : 0.f;
                sacc[nf][1] += (kg + 1 <= qg0) ? MASKV : 0.f;
                sacc[nf][2] += (kg     <= qg1) ? MASKV : 0.f;
                sacc[nf][3] += (kg + 1 <= qg1) ? MASKV : 0.f;
            }
        }

        // ---- warp-local row max ----
        float m0 = fmaxf(sacc[0][0], sacc[0][1]);
        float m1 = fmaxf(sacc[0][2], sacc[0][3]);
#pragma unroll
        for (int nf = 1; nf < 8; nf++) {
            m0 = fmaxf(m0, fmaxf(sacc[nf][0], sacc[nf][1]));
            m1 = fmaxf(m1, fmaxf(sacc[nf][2], sacc[nf][3]));
        }
        m0 = fmaxf(m0, __shfl_xor_sync(0xffffffffu, m0, 1));
        m0 = fmaxf(m0, __shfl_xor_sync(0xffffffffu, m0, 2));
        m1 = fmaxf(m1, __shfl_xor_sync(0xffffffffu, m1, 1));
        m1 = fmaxf(m1, __shfl_xor_sync(0xffffffffu, m1, 2));

        const float mn0 = fmaxf(rowm0, m0);
        const float mn1 = fmaxf(rowm1, m1);
        const float alpha0 = exp2f(rowm0 - mn0);
        const float alpha1 = exp2f(rowm1 - mn1);

        // ---- p = exp2(s - mn) via packed fp16 ex2; fp32 sums ----
        uint32_t pf[4][4];
        float s0 = 0.f, s1 = 0.f;
#pragma unroll
        for (int nf = 0; nf < 8; nf++) {
            __half2 a01 = __floats2half2_rn(sacc[nf][0] - mn0, sacc[nf][1] - mn0);
            __half2 a23 = __floats2half2_rn(sacc[nf][2] - mn1, sacc[nf][3] - mn1);
            uint32_t p01, p23;
            EX2_F16X2(p01, *(uint32_t*)&a01);
            EX2_F16X2(p23, *(uint32_t*)&a23);
            pf[nf >> 1][((nf & 1) << 1) + 0] = p01;
            pf[nf >> 1][((nf & 1) << 1) + 1] = p23;
            float2 f01 = __half22float2(*(__half2*)&p01);
            float2 f23 = __half22float2(*(__half2*)&p23);
            s0 += f01.x + f01.y;
            s1 += f23.x + f23.y;
        }
        s0 += __shfl_xor_sync(0xffffffffu, s0, 1);
        s0 += __shfl_xor_sync(0xffffffffu, s0, 2);
        s1 += __shfl_xor_sync(0xffffffffu, s1, 1);
        s1 += __shfl_xor_sync(0xffffffffu, s1, 2);
        rowl0 = rowl0 * alpha0 + s0;
        rowl1 = rowl1 * alpha1 + s1;
        rowm0 = mn0;
        rowm1 = mn1;

#pragma unroll
        for (int j = 0; j < 16; j++) {
            acc_o[j][0] *= alpha0; acc_o[j][1] *= alpha0;
            acc_o[j][2] *= alpha1; acc_o[j][3] *= alpha1;
        }

        // ---- O (16x128) += P * V ----
#pragma unroll
        for (int kc = 0; kc < 4; kc++) {
            uint32_t krow = (uint32_t)(kc * 16 + ((grp & 1) << 3) + li);
#pragma unroll
            for (int nf2 = 0; nf2 < 8; nf2++) {
                uint32_t bvh[4];
                uint32_t nb = (uint32_t)((nf2 * 16 + ((grp >> 1) << 3)) * 2);
                LDMX4T(bvh, vstg + krow * 272 + nb);
                MMA_F16(acc_o[2 * nf2],     pf[kc], bvh[0], bvh[1]);
                MMA_F16(acc_o[2 * nf2 + 1], pf[kc], bvh[2], bvh[3]);
            }
        }
        BAR_G(g);

        if (i + 2 < n) ISSUE_KV_G(kt0 + g + 2 * (i + 2), i & 1);
        CP_COMMIT();
    }

    // ---- merge the two groups (exact split-KV combine, log2 units) ----
    float* Ored = (float*)(smc + A_ST + 2 * ST_SZ);
    float* Mst = Ored + 64 * 128;
    float* Lst = Mst + 64;
    if (g == 1) {
#pragma unroll
        for (int nf = 0; nf < 16; nf++) {
            int col = nf * 8 + 2 * q;
            *(float2*)&Ored[r0 * 128 + col] = make_float2(acc_o[nf][0], acc_o[nf][1]);
            *(float2*)&Ored[r1 * 128 + col] = make_float2(acc_o[nf][2], acc_o[nf][3]);
        }
        if (q == 0) {
            Mst[r0] = rowm0; Lst[r0] = rowl0;
            Mst[r1] = rowm1; Lst[r1] = rowl1;
        }
    }
    __syncthreads();
    if (g == 0) {
        const float mB0 = Mst[r0], lB0 = Lst[r0];
        const float mB1 = Mst[r1], lB1 = Lst[r1];
        const float mm0 = fmaxf(rowm0, mB0), mm1 = fmaxf(rowm1, mB1);
        const float fa0 = exp2f(rowm0 - mm0), fb0 = exp2f(mB0 - mm0);
        const float fa1 = exp2f(rowm1 - mm1), fb1 = exp2f(mB1 - mm1);
        const float l0 = rowl0 * fa0 + lB0 * fb0;
        const float l1 = rowl1 * fa1 + lB1 * fb1;
        const int grow0 = b * TSEQ + qt * 64 + r0;
        const float scl0 = (1.f / l0) * mask[(size_t)b * TSEQ + qt * 64 + r0];
        const float scl1 = (1.f / l1) * mask[(size_t)b * TSEQ + qt * 64 + r1];
#pragma unroll
        for (int nf = 0; nf < 16; nf++) {
            int col = nf * 8 + 2 * q;
            float2 pr0 = *(float2*)&Ored[r0 * 128 + col];
            float2 pr1 = *(float2*)&Ored[r1 * 128 + col];
            float2 w0 = make_float2((acc_o[nf][0] * fa0 + pr0.x * fb0) * scl0,
                                    (acc_o[nf][1] * fa0 + pr0.y * fb0) * scl0);
            float2 w1 = make_float2((acc_o[nf][2] * fa1 + pr1.x * fb1) * scl1,
                                    (acc_o[nf][3] * fa1 + pr1.y * fb1) * scl1);
            *(float2*)&out[(size_t)grow0 * DMOD + h * DH + col] = w0;
            *(float2*)&out[(size_t)(grow0 + 8) * DMOD + h * DH + col] = w1;
        }
    }
}

extern "C" void kernel_launch(void* const* d_in, const int* in_sizes, int n_in,
                              void* d_out, int out_size) {
    const float* x    = (const float*)d_in[0];
    const float* mask = (const float*)d_in[1];
    const float* Wq   = (const float*)d_in[2];
    const float* Wk   = (const float*)d_in[3];
    const float* Wv   = (const float*)d_in[4];
    float* out = (float*)d_out;

    __half *xh, *wh, *qh, *kh, *vh;
    cudaGetSymbolAddress((void**)&xh, g_Xh);
    cudaGetSymbolAddress((void**)&wh, g_Wh);
    cudaGetSymbolAddress((void**)&qh, g_Qh);
    cudaGetSymbolAddress((void**)&kh, g_Kh);
    cudaGetSymbolAddress((void**)&vh, g_Vh);

    cudaFuncSetAttribute(gemm_qkv_f16, cudaFuncAttributeMaxDynamicSharedMemorySize,
                         GEMM_SMEM);
    cudaFuncSetAttribute(attn_tc, cudaFuncAttributeMaxDynamicSharedMemorySize,
                         ATTN_SMEM);

    cvt_all<<<8192 + 3 * 1024, 256>>>((const float4*)x, (const float4*)Wq,
                                      (const float4*)Wk, (const float4*)Wv,
                                      (uint2*)xh, (uint2*)wh);

    dim3 ggrid(3 * DMOD / 128, (BATCH * TSEQ) / 128);
    gemm_qkv_f16<<<ggrid, 256, GEMM_SMEM>>>(xh, wh, qh, kh, vh);

    dim3 agrid(TSEQ / 64, NH, BATCH);
    attn_tc<<<agrid, 256, ATTN_SMEM>>>(mask, out);
}

// round 16
// speedup vs baseline: 1.1259x; 1.0474x over previous
#include <cuda_runtime.h>
#include <cuda_bf16.h>
#include <cuda_fp16.h>
#include <cstdint>

#define BATCH 8
#define TSEQ 1024
#define DMOD 1024
#define NH 8
#define DH 128
#define SCALE 0.08838834764831845f
#define LOG2E 1.4426950408889634f
#define MASKV (-10000.0f * LOG2E)

__device__ __half g_Xh[BATCH * TSEQ * DMOD];
__device__ __half g_Wh[3 * DMOD * DMOD];
__device__ __half g_Qh[BATCH * TSEQ * DMOD];
__device__ __half g_Kh[BATCH * TSEQ * DMOD];
__device__ __half g_Vh[BATCH * TSEQ * DMOD];

__device__ __forceinline__ uint32_t smem_u32(const void* p) {
    uint32_t a;
    asm("{ .reg .u64 t; cvta.to.shared.u64 t, %1; cvt.u32.u64 %0, t; }"
        : "=r"(a) : "l"(p));
    return a;
}
__device__ __forceinline__ void cp16(uint32_t dst, const void* src) {
    asm volatile("cp.async.cg.shared.global [%0], [%1], 16;"
                 :: "r"(dst), "l"(src) : "memory");
}
#define CP_COMMIT() asm volatile("cp.async.commit_group;" ::: "memory")
#define CP_WAIT(n)  asm volatile("cp.async.wait_group %0;" :: "n"(n) : "memory")

#define MMA_F16(c, a, b0_, b1_) \
    asm volatile("mma.sync.aligned.m16n8k16.row.col.f32.f16.f16.f32 " \
                 "{%0,%1,%2,%3}, {%4,%5,%6,%7}, {%8,%9}, {%0,%1,%2,%3};" \
                 : "+f"((c)[0]), "+f"((c)[1]), "+f"((c)[2]), "+f"((c)[3]) \
                 : "r"((a)[0]), "r"((a)[1]), "r"((a)[2]), "r"((a)[3]), \
                   "r"(b0_), "r"(b1_))

#define LDMX4(r, addr) \
    asm volatile("ldmatrix.sync.aligned.m8n8.x4.shared.b16 {%0,%1,%2,%3}, [%4];" \
                 : "=r"((r)[0]), "=r"((r)[1]), "=r"((r)[2]), "=r"((r)[3]) : "r"(addr))
#define LDMX4T(r, addr) \
    asm volatile("ldmatrix.sync.aligned.m8n8.x4.trans.shared.b16 {%0,%1,%2,%3}, [%4];" \
                 : "=r"((r)[0]), "=r"((r)[1]), "=r"((r)[2]), "=r"((r)[3]) : "r"(addr))

#define EX2_F16X2(d, a) \
    asm("ex2.approx.f16x2 %0, %1;" : "=r"(d) : "r"(a))

// ===========================================================================
// Fused conversion: X (8192 blocks) then Wq/Wk/Wv (1024 each).
// ===========================================================================
__global__ __launch_bounds__(256) void cvt_all(const float4* __restrict__ x,
                                               const float4* __restrict__ w0,
                                               const float4* __restrict__ w1,
                                               const float4* __restrict__ w2,
                                               uint2* __restrict__ xh,
                                               uint2* __restrict__ wh) {
    int bi = blockIdx.x;
    const float4* src;
    uint2* dst;
    int i;
    if (bi < 8192) {
        i = bi * 256 + threadIdx.x;
        src = x;
        dst = xh;
    } else {
        int wsel = (bi - 8192) >> 10;
        i = ((bi - 8192) & 1023) * 256 + threadIdx.x;
        src = (wsel == 0) ? w0 : (wsel == 1) ? w1 : w2;
        dst = wh + (size_t)wsel * (DMOD * DMOD / 4);
    }
    float4 v = src[i];
    __half2 p01 = __floats2half2_rn(v.x, v.y);
    __half2 p23 = __floats2half2_rn(v.z, v.w);
    uint2 H;
    H.x = *(uint32_t*)&p01;
    H.y = *(uint32_t*)&p23;
    dst[i] = H;
}

// ===========================================================================
// Fused QKV GEMM (HW MAC floor). SCALE*log2e folded into Q epilogue.
// ===========================================================================
#define GTILE 10240
#define GSTAGE (2 * GTILE)
#define GEMM_SMEM (2 * GSTAGE)

__global__ __launch_bounds__(256, 2) void gemm_qkv_f16(
    const __half* __restrict__ Xh, const __half* __restrict__ Wh,
    __half* __restrict__ qh, __half* __restrict__ kh, __half* __restrict__ vh) {
    extern __shared__ char smc[];
    const uint32_t sb = smem_u32(smc);

    const int tid = threadIdx.x;
    const int lane = tid & 31, wid = tid >> 5;
    const int bm = blockIdx.y << 7;
    const int bnG = blockIdx.x << 7;
    const int wm = (wid & 1) * 64, wn = (wid >> 1) * 32;
    const int fm = lane >> 2;
    const int fkb = (lane & 3) * 4;
    const int grp = lane >> 3, li = lane & 7;

    float acc[4][4][4];
#pragma unroll
    for (int i = 0; i < 4; i++)
#pragma unroll
        for (int j = 0; j < 4; j++)
#pragma unroll
            for (int q = 0; q < 4; q++) acc[i][j][q] = 0.f;

    const int c0row = tid >> 2;
    const int c1row = c0row + 64;
    const int ce = (tid & 3) * 8;
    const uint32_t d0 = (uint32_t)(c0row * 80 + (tid & 3) * 16);
    const uint32_t d1 = (uint32_t)(c1row * 80 + (tid & 3) * 16);

#define ISSUE_STAGE(kt, p) do {                                        \
    uint32_t s0 = sb + (p) * GSTAGE;                                   \
    size_t a0 = (size_t)(bm + c0row) * 1024 + (size_t)(kt) * 32 + ce;  \
    size_t a1 = (size_t)(bm + c1row) * 1024 + (size_t)(kt) * 32 + ce;  \
    size_t b0 = (size_t)(bnG + c0row) * 1024 + (size_t)(kt) * 32 + ce; \
    size_t b1 = (size_t)(bnG + c1row) * 1024 + (size_t)(kt) * 32 + ce; \
    cp16(s0 + d0,         Xh + a0);  cp16(s0 + d1,         Xh + a1);   \
    cp16(s0 + GTILE + d0, Wh + b0);  cp16(s0 + GTILE + d1, Wh + b1);   \
    CP_COMMIT();                                                       \
} while (0)

    ISSUE_STAGE(0, 0);

    for (int kt = 0; kt < 32; kt++) {
        const int p = kt & 1;
        if (kt < 31) {
            ISSUE_STAGE(kt + 1, p ^ 1);
            CP_WAIT(1);
        } else {
            CP_WAIT(0);
        }
        __syncthreads();

        const uint32_t st = sb + p * GSTAGE;
#pragma unroll
        for (int k16o = 0; k16o < 64; k16o += 32) {
            uint32_t ah[4][4], bh[2][4];
            const uint32_t akb = (uint32_t)(k16o + ((grp >> 1) << 4));
            const uint32_t bkb = (uint32_t)(k16o + ((grp & 1) << 4));
#pragma unroll
            for (int np = 0; np < 2; np++) {
                uint32_t nrow = (uint32_t)(wn + np * 16 + ((grp >> 1) << 3) + li);
                LDMX4(bh[np], st + GTILE + nrow * 80 + bkb);
            }
#pragma unroll
            for (int mt = 0; mt < 4; mt++) {
                uint32_t arow = (uint32_t)(wm + mt * 16 + ((grp & 1) << 3) + li);
                LDMX4(ah[mt], st + arow * 80 + akb);
            }
#pragma unroll
            for (int mt = 0; mt < 4; mt++)
#pragma unroll
                for (int nt = 0; nt < 4; nt++)
                    MMA_F16(acc[mt][nt], ah[mt], bh[nt >> 1][(nt & 1) * 2],
                            bh[nt >> 1][(nt & 1) * 2 + 1]);
        }
        __syncthreads();
    }

    const int which = bnG >> 10;
    const int nloc = bnG & 1023;
    __half* C = (which == 0) ? qh : (which == 1) ? kh : vh;
    const float escl = (which == 0) ? (SCALE * LOG2E) : 1.f;

#pragma unroll
    for (int mt = 0; mt < 4; mt++) {
        size_t m0 = (size_t)(bm + wm + mt * 16 + fm);
#pragma unroll
        for (int nt = 0; nt < 4; nt++) {
            size_t n0 = (size_t)(nloc + wn + nt * 8 + (fkb >> 1));
            __half2 p01 = __floats2half2_rn(acc[mt][nt][0] * escl, acc[mt][nt][1] * escl);
            __half2 p23 = __floats2half2_rn(acc[mt][nt][2] * escl, acc[mt][nt][3] * escl);
            *(uint32_t*)((char*)C + (m0 * 1024 + n0) * 2) = *(uint32_t*)&p01;
            *(uint32_t*)((char*)C + ((m0 + 8) * 1024 + n0) * 2) = *(uint32_t*)&p23;
        }
    }
}

// ===========================================================================
// Flash attention: 128-thread CTAs (4 warps, 64 q-rows, full KV pass),
// 2 CTAs/SM co-resident. Warp owns complete rows -> warp-local softmax
// (log2 domain, packed ex2). Double-buffered cp.async KV. No merge epilogue.
// ===========================================================================
#define A_QH 0
#define A_ST 17408
#define ST_SZ 34816
#define ATTN_SMEM (17408 + 2 * 34816)   // 87040

__global__ __launch_bounds__(128, 2) void attn_tc(const float* __restrict__ mask,
                                                  float* __restrict__ out) {
    extern __shared__ char smc[];
    const uint32_t sb = smem_u32(smc);

    const int tid = threadIdx.x;
    const int lane = tid & 31, wid = tid >> 5;
    const int qt = (blockIdx.x == 0) ? 15 : (int)blockIdx.x - 1;
    const int h = blockIdx.y, b = blockIdx.z;
    const int wm = wid * 16;
    const int fm = lane >> 2, q = lane & 3;
    const int grp = lane >> 3, li = lane & 7;
    const int r0 = wm + fm, r1 = r0 + 8;

    const size_t bh_off = (size_t)b * TSEQ * DMOD + (size_t)h * DH;
    const __half* Qh = g_Qh + bh_off;
    const __half* Kh = g_Kh + bh_off;
    const __half* Vh = g_Vh + bh_off;

    const int kt0 = (qt == 15) ? 0 : qt;

    // Q tile -> smem (commit group 0)
    for (int c = tid; c < 1024; c += 128) {
        int r = c >> 4, o = c & 15;
        cp16(sb + A_QH + (uint32_t)(r * 272 + o * 16),
             Qh + (size_t)(qt * 64 + r) * DMOD + o * 8);
    }
    CP_COMMIT();

#define ISSUE_KV(kt_, s_) do {                                           \
    uint32_t kst = sb + A_ST + (uint32_t)(s_) * ST_SZ;                   \
    size_t roff = (size_t)(kt_) * 64 * DMOD;                             \
    for (int c = tid; c < 1024; c += 128) {                              \
        int r = c >> 4, o = c & 15;                                      \
        uint32_t d = (uint32_t)(r * 272 + o * 16);                       \
        size_t gaddr = roff + (size_t)r * DMOD + o * 8;                  \
        cp16(kst + d,         Kh + gaddr);                               \
        cp16(kst + 17408 + d, Vh + gaddr);                               \
    }                                                                    \
} while (0)

    ISSUE_KV(kt0, 0);
    CP_COMMIT();
    if (kt0 + 1 <= 15) ISSUE_KV(kt0 + 1, 1);
    CP_COMMIT();

    CP_WAIT(2);                // Q complete
    __syncthreads();

    // Persistent Q fragments (SCALE*log2e pre-folded)
    uint32_t Qf[8][4];
    {
        uint32_t arow = (uint32_t)(wm + ((grp & 1) << 3) + li);
#pragma unroll
        for (int ks = 0; ks < 8; ks++) {
            uint32_t akb = (uint32_t)(ks * 32 + ((grp >> 1) << 4));
            LDMX4(Qf[ks], sb + A_QH + arow * 272 + akb);
        }
    }

    float rowm0 = -1e30f, rowm1 = -1e30f, rowl0 = 0.f, rowl1 = 0.f;
    float acc_o[16][4];
#pragma unroll
    for (int j = 0; j < 16; j++)
#pragma unroll
        for (int qq = 0; qq < 4; qq++) acc_o[j][qq] = 0.f;

    for (int kt = kt0; kt < 16; kt++) {
        const int p = (kt - kt0) & 1;
        const uint32_t kstg = sb + A_ST + (uint32_t)p * ST_SZ;
        const uint32_t vstg = kstg + 17408;

        if (kt == 15) { CP_WAIT(0); } else { CP_WAIT(1); }
        __syncthreads();                       // stage ready

        // ---- S (16x64) = Q * K^T  (log2 units) ----
        float sacc[8][4];
#pragma unroll
        for (int j = 0; j < 8; j++)
#pragma unroll
            for (int qq = 0; qq < 4; qq++) sacc[j][qq] = 0.f;

#pragma unroll
        for (int ks = 0; ks < 8; ks++) {
            uint32_t bh[4][4];
            uint32_t kb = (uint32_t)(ks * 32 + ((grp & 1) << 4));
#pragma unroll
            for (int nf = 0; nf < 4; nf++) {
                uint32_t nrow = (uint32_t)(nf * 16 + ((grp >> 1) << 3) + li);
                LDMX4(bh[nf], kstg + nrow * 272 + kb);
            }
#pragma unroll
            for (int nf = 0; nf < 4; nf++) {
                MMA_F16(sacc[2 * nf],     Qf[ks], bh[nf][0], bh[nf][1]);
                MMA_F16(sacc[2 * nf + 1], Qf[ks], bh[nf][2], bh[nf][3]);
            }
        }

        // ---- causal mask ----
        {
            const int qg0 = qt * 64 + r0, qg1 = qg0 + 8;
#pragma unroll
            for (int nf = 0; nf < 8; nf++) {
                int kg = kt * 64 + nf * 8 + 2 * q;
                sacc[nf][0] += (kg     <= qg0) ? MASKV : 0.f;
                sacc[nf][1] += (kg + 1 <= qg0) ? MASKV : 0.f;
                sacc[nf][2] += (kg     <= qg1) ? MASKV : 0.f;
                sacc[nf][3] += (kg + 1 <= qg1) ? MASKV : 0.f;
            }
        }

        // ---- warp-local row max ----
        float m0 = fmaxf(sacc[0][0], sacc[0][1]);
        float m1 = fmaxf(sacc[0][2], sacc[0][3]);
#pragma unroll
        for (int nf = 1; nf < 8; nf++) {
            m0 = fmaxf(m0, fmaxf(sacc[nf][0], sacc[nf][1]));
            m1 = fmaxf(m1, fmaxf(sacc[nf][2], sacc[nf][3]));
        }
        m0 = fmaxf(m0, __shfl_xor_sync(0xffffffffu, m0, 1));
        m0 = fmaxf(m0, __shfl_xor_sync(0xffffffffu, m0, 2));
        m1 = fmaxf(m1, __shfl_xor_sync(0xffffffffu, m1, 1));
        m1 = fmaxf(m1, __shfl_xor_sync(0xffffffffu, m1, 2));

        const float mn0 = fmaxf(rowm0, m0);
        const float mn1 = fmaxf(rowm1, m1);
        const float alpha0 = exp2f(rowm0 - mn0);
        const float alpha1 = exp2f(rowm1 - mn1);

        // ---- p = exp2(s - mn) packed fp16; fp32 sums ----
        uint32_t pf[4][4];
        float s0 = 0.f, s1 = 0.f;
#pragma unroll
        for (int nf = 0; nf < 8; nf++) {
            __half2 a01 = __floats2half2_rn(sacc[nf][0] - mn0, sacc[nf][1] - mn0);
            __half2 a23 = __floats2half2_rn(sacc[nf][2] - mn1, sacc[nf][3] - mn1);
            uint32_t p01, p23;
            EX2_F16X2(p01, *(uint32_t*)&a01);
            EX2_F16X2(p23, *(uint32_t*)&a23);
            pf[nf >> 1][((nf & 1) << 1) + 0] = p01;
            pf[nf >> 1][((nf & 1) << 1) + 1] = p23;
            float2 f01 = __half22float2(*(__half2*)&p01);
            float2 f23 = __half22float2(*(__half2*)&p23);
            s0 += f01.x + f01.y;
            s1 += f23.x + f23.y;
        }
        s0 += __shfl_xor_sync(0xffffffffu, s0, 1);
        s0 += __shfl_xor_sync(0xffffffffu, s0, 2);
        s1 += __shfl_xor_sync(0xffffffffu, s1, 1);
        s1 += __shfl_xor_sync(0xffffffffu, s1, 2);
        rowl0 = rowl0 * alpha0 + s0;
        rowl1 = rowl1 * alpha1 + s1;
        rowm0 = mn0;
        rowm1 = mn1;

#pragma unroll
        for (int j = 0; j < 16; j++) {
            acc_o[j][0] *= alpha0; acc_o[j][1] *= alpha0;
            acc_o[j][2] *= alpha1; acc_o[j][3] *= alpha1;
        }

        // ---- O (16x128) += P * V ----
#pragma unroll
        for (int kc = 0; kc < 4; kc++) {
            uint32_t krow = (uint32_t)(kc * 16 + ((grp & 1) << 3) + li);
#pragma unroll
            for (int nf2 = 0; nf2 < 8; nf2++) {
                uint32_t bvh[4];
                uint32_t nb = (uint32_t)((nf2 * 16 + ((grp >> 1) << 3)) * 2);
                LDMX4T(bvh, vstg + krow * 272 + nb);
                MMA_F16(acc_o[2 * nf2],     pf[kc], bvh[0], bvh[1]);
                MMA_F16(acc_o[2 * nf2 + 1], pf[kc], bvh[2], bvh[3]);
            }
        }
        __syncthreads();                       // stage consumed

        if (kt + 2 <= 15) {
            ISSUE_KV(kt + 2, p);
        }
        CP_COMMIT();
    }

    // ---- direct epilogue (no merge) ----
    {
        const int grow0 = b * TSEQ + qt * 64 + r0;
        const float scl0 = (1.f / rowl0) * mask[(size_t)b * TSEQ + qt * 64 + r0];
        const float scl1 = (1.f / rowl1) * mask[(size_t)b * TSEQ + qt * 64 + r1];
#pragma unroll
        for (int nf = 0; nf < 16; nf++) {
            int col = nf * 8 + 2 * q;
            float2 w0 = make_float2(acc_o[nf][0] * scl0, acc_o[nf][1] * scl0);
            float2 w1 = make_float2(acc_o[nf][2] * scl1, acc_o[nf][3] * scl1);
            *(float2*)&out[(size_t)grow0 * DMOD + h * DH + col] = w0;
            *(float2*)&out[(size_t)(grow0 + 8) * DMOD + h * DH + col] = w1;
        }
    }
}

extern "C" void kernel_launch(void* const* d_in, const int* in_sizes, int n_in,
                              void* d_out, int out_size) {
    const float* x    = (const float*)d_in[0];
    const float* mask = (const float*)d_in[1];
    const float* Wq   = (const float*)d_in[2];
    const float* Wk   = (const float*)d_in[3];
    const float* Wv   = (const float*)d_in[4];
    float* out = (float*)d_out;

    __half *xh, *wh, *qh, *kh, *vh;
    cudaGetSymbolAddress((void**)&xh, g_Xh);
    cudaGetSymbolAddress((void**)&wh, g_Wh);
    cudaGetSymbolAddress((void**)&qh, g_Qh);
    cudaGetSymbolAddress((void**)&kh, g_Kh);
    cudaGetSymbolAddress((void**)&vh, g_Vh);

    cudaFuncSetAttribute(gemm_qkv_f16, cudaFuncAttributeMaxDynamicSharedMemorySize,
                         GEMM_SMEM);
    cudaFuncSetAttribute(attn_tc, cudaFuncAttributeMaxDynamicSharedMemorySize,
                         ATTN_SMEM);

    cvt_all<<<8192 + 3 * 1024, 256>>>((const float4*)x, (const float4*)Wq,
                                      (const float4*)Wk, (const float4*)Wv,
                                      (uint2*)xh, (uint2*)wh);

    dim3 ggrid(3 * DMOD / 128, (BATCH * TSEQ) / 128);
    gemm_qkv_f16<<<ggrid, 256, GEMM_SMEM>>>(xh, wh, qh, kh, vh);

    dim3 agrid(TSEQ / 64, NH, BATCH);
    attn_tc<<<agrid, 128, ATTN_SMEM>>>(mask, out);
}

// round 17
// speedup vs baseline: 1.1389x; 1.0116x over previous
#include <cuda_runtime.h>
#include <cuda_bf16.h>
#include <cuda_fp16.h>
#include <cstdint>

#define BATCH 8
#define TSEQ 1024
#define DMOD 1024
#define NH 8
#define DH 128
#define SCALE 0.08838834764831845f
#define LOG2E 1.4426950408889634f
#define MASKV (-10000.0f * LOG2E)

__device__ __half g_Xh[BATCH * TSEQ * DMOD];
__device__ __half g_Wh[3 * DMOD * DMOD];
__device__ __half g_Qh[BATCH * TSEQ * DMOD];
__device__ __half g_Kh[BATCH * TSEQ * DMOD];
__device__ __half g_Vh[BATCH * TSEQ * DMOD];

__device__ __forceinline__ uint32_t smem_u32(const void* p) {
    uint32_t a;
    asm("{ .reg .u64 t; cvta.to.shared.u64 t, %1; cvt.u32.u64 %0, t; }"
        : "=r"(a) : "l"(p));
    return a;
}
__device__ __forceinline__ void cp16(uint32_t dst, const void* src) {
    asm volatile("cp.async.cg.shared.global [%0], [%1], 16;"
                 :: "r"(dst), "l"(src) : "memory");
}
#define CP_COMMIT() asm volatile("cp.async.commit_group;" ::: "memory")
#define CP_WAIT(n)  asm volatile("cp.async.wait_group %0;" :: "n"(n) : "memory")

#define MMA_F16(c, a, b0_, b1_) \
    asm volatile("mma.sync.aligned.m16n8k16.row.col.f32.f16.f16.f32 " \
                 "{%0,%1,%2,%3}, {%4,%5,%6,%7}, {%8,%9}, {%0,%1,%2,%3};" \
                 : "+f"((c)[0]), "+f"((c)[1]), "+f"((c)[2]), "+f"((c)[3]) \
                 : "r"((a)[0]), "r"((a)[1]), "r"((a)[2]), "r"((a)[3]), \
                   "r"(b0_), "r"(b1_))

#define LDMX4(r, addr) \
    asm volatile("ldmatrix.sync.aligned.m8n8.x4.shared.b16 {%0,%1,%2,%3}, [%4];" \
                 : "=r"((r)[0]), "=r"((r)[1]), "=r"((r)[2]), "=r"((r)[3]) : "r"(addr))
#define LDMX4T(r, addr) \
    asm volatile("ldmatrix.sync.aligned.m8n8.x4.trans.shared.b16 {%0,%1,%2,%3}, [%4];" \
                 : "=r"((r)[0]), "=r"((r)[1]), "=r"((r)[2]), "=r"((r)[3]) : "r"(addr))

#define EX2_F16X2(d, a) \
    asm("ex2.approx.f16x2 %0, %1;" : "=r"(d) : "r"(a))

// ===========================================================================
// Fused conversion: X (8192 blocks) then Wq/Wk/Wv (1024 each).
// ===========================================================================
__global__ __launch_bounds__(256) void cvt_all(const float4* __restrict__ x,
                                               const float4* __restrict__ w0,
                                               const float4* __restrict__ w1,
                                               const float4* __restrict__ w2,
                                               uint2* __restrict__ xh,
                                               uint2* __restrict__ wh) {
    int bi = blockIdx.x;
    const float4* src;
    uint2* dst;
    int i;
    if (bi < 8192) {
        i = bi * 256 + threadIdx.x;
        src = x;
        dst = xh;
    } else {
        int wsel = (bi - 8192) >> 10;
        i = ((bi - 8192) & 1023) * 256 + threadIdx.x;
        src = (wsel == 0) ? w0 : (wsel == 1) ? w1 : w2;
        dst = wh + (size_t)wsel * (DMOD * DMOD / 4);
    }
    float4 v = src[i];
    __half2 p01 = __floats2half2_rn(v.x, v.y);
    __half2 p23 = __floats2half2_rn(v.z, v.w);
    uint2 H;
    H.x = *(uint32_t*)&p01;
    H.y = *(uint32_t*)&p23;
    dst[i] = H;
}

// ===========================================================================
// Fused QKV GEMM (at mma.sync issue floor). SCALE*log2e folded into Q.
// ===========================================================================
#define GTILE 10240
#define GSTAGE (2 * GTILE)
#define GEMM_SMEM (2 * GSTAGE)

__global__ __launch_bounds__(256, 2) void gemm_qkv_f16(
    const __half* __restrict__ Xh, const __half* __restrict__ Wh,
    __half* __restrict__ qh, __half* __restrict__ kh, __half* __restrict__ vh) {
    extern __shared__ char smc[];
    const uint32_t sb = smem_u32(smc);

    const int tid = threadIdx.x;
    const int lane = tid & 31, wid = tid >> 5;
    const int bm = blockIdx.y << 7;
    const int bnG = blockIdx.x << 7;
    const int wm = (wid & 1) * 64, wn = (wid >> 1) * 32;
    const int fm = lane >> 2;
    const int fkb = (lane & 3) * 4;
    const int grp = lane >> 3, li = lane & 7;

    float acc[4][4][4];
#pragma unroll
    for (int i = 0; i < 4; i++)
#pragma unroll
        for (int j = 0; j < 4; j++)
#pragma unroll
            for (int q = 0; q < 4; q++) acc[i][j][q] = 0.f;

    const int c0row = tid >> 2;
    const int c1row = c0row + 64;
    const int ce = (tid & 3) * 8;
    const uint32_t d0 = (uint32_t)(c0row * 80 + (tid & 3) * 16);
    const uint32_t d1 = (uint32_t)(c1row * 80 + (tid & 3) * 16);

#define ISSUE_STAGE(kt, p) do {                                        \
    uint32_t s0 = sb + (p) * GSTAGE;                                   \
    size_t a0 = (size_t)(bm + c0row) * 1024 + (size_t)(kt) * 32 + ce;  \
    size_t a1 = (size_t)(bm + c1row) * 1024 + (size_t)(kt) * 32 + ce;  \
    size_t b0 = (size_t)(bnG + c0row) * 1024 + (size_t)(kt) * 32 + ce; \
    size_t b1 = (size_t)(bnG + c1row) * 1024 + (size_t)(kt) * 32 + ce; \
    cp16(s0 + d0,         Xh + a0);  cp16(s0 + d1,         Xh + a1);   \
    cp16(s0 + GTILE + d0, Wh + b0);  cp16(s0 + GTILE + d1, Wh + b1);   \
    CP_COMMIT();                                                       \
} while (0)

    ISSUE_STAGE(0, 0);

    for (int kt = 0; kt < 32; kt++) {
        const int p = kt & 1;
        if (kt < 31) {
            ISSUE_STAGE(kt + 1, p ^ 1);
            CP_WAIT(1);
        } else {
            CP_WAIT(0);
        }
        __syncthreads();

        const uint32_t st = sb + p * GSTAGE;
#pragma unroll
        for (int k16o = 0; k16o < 64; k16o += 32) {
            uint32_t ah[4][4], bh[2][4];
            const uint32_t akb = (uint32_t)(k16o + ((grp >> 1) << 4));
            const uint32_t bkb = (uint32_t)(k16o + ((grp & 1) << 4));
#pragma unroll
            for (int np = 0; np < 2; np++) {
                uint32_t nrow = (uint32_t)(wn + np * 16 + ((grp >> 1) << 3) + li);
                LDMX4(bh[np], st + GTILE + nrow * 80 + bkb);
            }
#pragma unroll
            for (int mt = 0; mt < 4; mt++) {
                uint32_t arow = (uint32_t)(wm + mt * 16 + ((grp & 1) << 3) + li);
                LDMX4(ah[mt], st + arow * 80 + akb);
            }
#pragma unroll
            for (int mt = 0; mt < 4; mt++)
#pragma unroll
                for (int nt = 0; nt < 4; nt++)
                    MMA_F16(acc[mt][nt], ah[mt], bh[nt >> 1][(nt & 1) * 2],
                            bh[nt >> 1][(nt & 1) * 2 + 1]);
        }
        __syncthreads();
    }

    const int which = bnG >> 10;
    const int nloc = bnG & 1023;
    __half* C = (which == 0) ? qh : (which == 1) ? kh : vh;
    const float escl = (which == 0) ? (SCALE * LOG2E) : 1.f;

#pragma unroll
    for (int mt = 0; mt < 4; mt++) {
        size_t m0 = (size_t)(bm + wm + mt * 16 + fm);
#pragma unroll
        for (int nt = 0; nt < 4; nt++) {
            size_t n0 = (size_t)(nloc + wn + nt * 8 + (fkb >> 1));
            __half2 p01 = __floats2half2_rn(acc[mt][nt][0] * escl, acc[mt][nt][1] * escl);
            __half2 p23 = __floats2half2_rn(acc[mt][nt][2] * escl, acc[mt][nt][3] * escl);
            *(uint32_t*)((char*)C + (m0 * 1024 + n0) * 2) = *(uint32_t*)&p01;
            *(uint32_t*)((char*)C + ((m0 + 8) * 1024 + n0) * 2) = *(uint32_t*)&p23;
        }
    }
}

// ===========================================================================
// Flash attention: 128-thread CTAs, 3 CTAs/SM target.
// Q fragments loaded directly from gmem (no Q smem). K/V in XOR-swizzled
// 256B-row smem (conflict-free ldmatrix, no padding). Double-buffered.
// ===========================================================================
#define ST_SZ 32768                 // K 16384 + V 16384, swizzled 256B rows
#define ATTN_SMEM (2 * ST_SZ)       // 65536

__global__ __launch_bounds__(128, 3) void attn_tc(const float* __restrict__ mask,
                                                  float* __restrict__ out) {
    extern __shared__ char smc[];
    const uint32_t sb = smem_u32(smc);

    const int tid = threadIdx.x;
    const int lane = tid & 31, wid = tid >> 5;
    const int qt = (blockIdx.x == 0) ? 15 : (int)blockIdx.x - 1;
    const int h = blockIdx.y, b = blockIdx.z;
    const int wm = wid * 16;
    const int fm = lane >> 2, q = lane & 3;
    const int grp = lane >> 3, li = lane & 7;
    const int r0 = wm + fm, r1 = r0 + 8;

    const size_t bh_off = (size_t)b * TSEQ * DMOD + (size_t)h * DH;
    const __half* Qh = g_Qh + bh_off;
    const __half* Kh = g_Kh + bh_off;
    const __half* Vh = g_Vh + bh_off;

    const int kt0 = (qt == 15) ? 0 : qt;

#define ISSUE_KV(kt_, s_) do {                                           \
    uint32_t kst = sb + (uint32_t)(s_) * ST_SZ;                          \
    size_t roff = (size_t)(kt_) * 64 * DMOD;                             \
    for (int c = tid; c < 1024; c += 128) {                              \
        int r = c >> 4, o = c & 15;                                      \
        uint32_t d = (uint32_t)(r * 256 + ((o ^ (r & 7)) << 4));         \
        size_t gaddr = roff + (size_t)r * DMOD + o * 8;                  \
        cp16(kst + d,         Kh + gaddr);                               \
        cp16(kst + 16384 + d, Vh + gaddr);                               \
    }                                                                    \
} while (0)

    ISSUE_KV(kt0, 0);
    CP_COMMIT();
    ISSUE_KV(kt0 + 1, 1);
    CP_COMMIT();

    // Q fragments direct from gmem (mapping == ldmatrix b16 A-fragment)
    uint32_t Qf[8][4];
    {
        const __half* Qr0 = Qh + (size_t)(qt * 64 + r0) * DMOD + 2 * q;
        const __half* Qr1 = Qh + (size_t)(qt * 64 + r1) * DMOD + 2 * q;
#pragma unroll
        for (int ks = 0; ks < 8; ks++) {
            Qf[ks][0] = *(const uint32_t*)(Qr0 + 16 * ks);
            Qf[ks][1] = *(const uint32_t*)(Qr1 + 16 * ks);
            Qf[ks][2] = *(const uint32_t*)(Qr0 + 16 * ks + 8);
            Qf[ks][3] = *(const uint32_t*)(Qr1 + 16 * ks + 8);
        }
    }

    float rowm0 = -1e30f, rowm1 = -1e30f, rowl0 = 0.f, rowl1 = 0.f;
    float acc_o[16][4];
#pragma unroll
    for (int j = 0; j < 16; j++)
#pragma unroll
        for (int qq = 0; qq < 4; qq++) acc_o[j][qq] = 0.f;

    for (int kt = kt0; kt < 16; kt++) {
        const int p = (kt - kt0) & 1;
        const uint32_t kstg = sb + (uint32_t)p * ST_SZ;
        const uint32_t vstg = kstg + 16384;

        if (kt == 15) { CP_WAIT(0); } else { CP_WAIT(1); }
        __syncthreads();                       // stage ready

        // ---- S (16x64) = Q * K^T  (log2 units) ----
        float sacc[8][4];
#pragma unroll
        for (int j = 0; j < 8; j++)
#pragma unroll
            for (int qq = 0; qq < 4; qq++) sacc[j][qq] = 0.f;

#pragma unroll
        for (int ks = 0; ks < 8; ks++) {
            uint32_t bh[4][4];
            uint32_t kb = (uint32_t)(ks * 32 + ((grp & 1) << 4));
            uint32_t kbs = kb ^ ((uint32_t)li << 4);
#pragma unroll
            for (int nf = 0; nf < 4; nf++) {
                uint32_t nrow = (uint32_t)(nf * 16 + ((grp >> 1) << 3) + li);
                LDMX4(bh[nf], kstg + nrow * 256 + kbs);
            }
#pragma unroll
            for (int nf = 0; nf < 4; nf++) {
                MMA_F16(sacc[2 * nf],     Qf[ks], bh[nf][0], bh[nf][1]);
                MMA_F16(sacc[2 * nf + 1], Qf[ks], bh[nf][2], bh[nf][3]);
            }
        }

        // ---- causal mask ----
        {
            const int qg0 = qt * 64 + r0, qg1 = qg0 + 8;
#pragma unroll
            for (int nf = 0; nf < 8; nf++) {
                int kg = kt * 64 + nf * 8 + 2 * q;
                sacc[nf][0] += (kg     <= qg0) ? MASKV : 0.f;
                sacc[nf][1] += (kg + 1 <= qg0) ? MASKV : 0.f;
                sacc[nf][2] += (kg     <= qg1) ? MASKV : 0.f;
                sacc[nf][3] += (kg + 1 <= qg1) ? MASKV : 0.f;
            }
        }

        // ---- warp-local row max ----
        float m0 = fmaxf(sacc[0][0], sacc[0][1]);
        float m1 = fmaxf(sacc[0][2], sacc[0][3]);
#pragma unroll
        for (int nf = 1; nf < 8; nf++) {
            m0 = fmaxf(m0, fmaxf(sacc[nf][0], sacc[nf][1]));
            m1 = fmaxf(m1, fmaxf(sacc[nf][2], sacc[nf][3]));
        }
        m0 = fmaxf(m0, __shfl_xor_sync(0xffffffffu, m0, 1));
        m0 = fmaxf(m0, __shfl_xor_sync(0xffffffffu, m0, 2));
        m1 = fmaxf(m1, __shfl_xor_sync(0xffffffffu, m1, 1));
        m1 = fmaxf(m1, __shfl_xor_sync(0xffffffffu, m1, 2));

        const float mn0 = fmaxf(rowm0, m0);
        const float mn1 = fmaxf(rowm1, m1);
        const float alpha0 = exp2f(rowm0 - mn0);
        const float alpha1 = exp2f(rowm1 - mn1);

        // ---- p = exp2(s - mn) packed fp16; fp32 sums ----
        uint32_t pf[4][4];
        float s0 = 0.f, s1 = 0.f;
#pragma unroll
        for (int nf = 0; nf < 8; nf++) {
            __half2 a01 = __floats2half2_rn(sacc[nf][0] - mn0, sacc[nf][1] - mn0);
            __half2 a23 = __floats2half2_rn(sacc[nf][2] - mn1, sacc[nf][3] - mn1);
            uint32_t p01, p23;
            EX2_F16X2(p01, *(uint32_t*)&a01);
            EX2_F16X2(p23, *(uint32_t*)&a23);
            pf[nf >> 1][((nf & 1) << 1) + 0] = p01;
            pf[nf >> 1][((nf & 1) << 1) + 1] = p23;
            float2 f01 = __half22float2(*(__half2*)&p01);
            float2 f23 = __half22float2(*(__half2*)&p23);
            s0 += f01.x + f01.y;
            s1 += f23.x + f23.y;
        }
        s0 += __shfl_xor_sync(0xffffffffu, s0, 1);
        s0 += __shfl_xor_sync(0xffffffffu, s0, 2);
        s1 += __shfl_xor_sync(0xffffffffu, s1, 1);
        s1 += __shfl_xor_sync(0xffffffffu, s1, 2);
        rowl0 = rowl0 * alpha0 + s0;
        rowl1 = rowl1 * alpha1 + s1;
        rowm0 = mn0;
        rowm1 = mn1;

#pragma unroll
        for (int j = 0; j < 16; j++) {
            acc_o[j][0] *= alpha0; acc_o[j][1] *= alpha0;
            acc_o[j][2] *= alpha1; acc_o[j][3] *= alpha1;
        }

        // ---- O (16x128) += P * V ----
#pragma unroll
        for (int kc = 0; kc < 4; kc++) {
            uint32_t krow = (uint32_t)(kc * 16 + ((grp & 1) << 3) + li);
#pragma unroll
            for (int nf2 = 0; nf2 < 8; nf2++) {
                uint32_t bvh[4];
                uint32_t nb = (uint32_t)((nf2 * 16 + ((grp >> 1) << 3)) * 2);
                LDMX4T(bvh, vstg + krow * 256 + (nb ^ ((uint32_t)li << 4)));
                MMA_F16(acc_o[2 * nf2],     pf[kc], bvh[0], bvh[1]);
                MMA_F16(acc_o[2 * nf2 + 1], pf[kc], bvh[2], bvh[3]);
            }
        }
        __syncthreads();                       // stage consumed

        if (kt + 2 <= 15) {
            ISSUE_KV(kt + 2, p);
        }
        CP_COMMIT();
    }

    // ---- direct epilogue ----
    {
        const int grow0 = b * TSEQ + qt * 64 + r0;
        const float scl0 = (1.f / rowl0) * mask[(size_t)b * TSEQ + qt * 64 + r0];
        const float scl1 = (1.f / rowl1) * mask[(size_t)b * TSEQ + qt * 64 + r1];
#pragma unroll
        for (int nf = 0; nf < 16; nf++) {
            int col = nf * 8 + 2 * q;
            float2 w0 = make_float2(acc_o[nf][0] * scl0, acc_o[nf][1] * scl0);
            float2 w1 = make_float2(acc_o[nf][2] * scl1, acc_o[nf][3] * scl1);
            *(float2*)&out[(size_t)grow0 * DMOD + h * DH + col] = w0;
            *(float2*)&out[(size_t)(grow0 + 8) * DMOD + h * DH + col] = w1;
        }
    }
}

extern "C" void kernel_launch(void* const* d_in, const int* in_sizes, int n_in,
                              void* d_out, int out_size) {
    const float* x    = (const float*)d_in[0];
    const float* mask = (const float*)d_in[1];
    const float* Wq   = (const float*)d_in[2];
    const float* Wk   = (const float*)d_in[3];
    const float* Wv   = (const float*)d_in[4];
    float* out = (float*)d_out;

    __half *xh, *wh, *qh, *kh, *vh;
    cudaGetSymbolAddress((void**)&xh, g_Xh);
    cudaGetSymbolAddress((void**)&wh, g_Wh);
    cudaGetSymbolAddress((void**)&qh, g_Qh);
    cudaGetSymbolAddress((void**)&kh, g_Kh);
    cudaGetSymbolAddress((void**)&vh, g_Vh);

    cudaFuncSetAttribute(gemm_qkv_f16, cudaFuncAttributeMaxDynamicSharedMemorySize,
                         GEMM_SMEM);
    cudaFuncSetAttribute(attn_tc, cudaFuncAttributeMaxDynamicSharedMemorySize,
                         ATTN_SMEM);

    cvt_all<<<8192 + 3 * 1024, 256>>>((const float4*)x, (const float4*)Wq,
                                      (const float4*)Wk, (const float4*)Wv,
                                      (uint2*)xh, (uint2*)wh);

    dim3 ggrid(3 * DMOD / 128, (BATCH * TSEQ) / 128);
    gemm_qkv_f16<<<ggrid, 256, GEMM_SMEM>>>(xh, wh, qh, kh, vh);

    dim3 agrid(TSEQ / 64, NH, BATCH);
    attn_tc<<<agrid, 128, ATTN_SMEM>>>(mask, out);
}